// round 1
// baseline (speedup 1.0000x reference)
#include <cuda_runtime.h>
#include <math.h>

#define NB      2
#define LSEQ    1024
#define DMODEL  1024
#define NHEAD   16
#define DHEAD   64
#define NLAY    6
#define VOCAB   30000
#define HIDB    512
#define FFDIM   4096
#define NROWS   2048   /* NB*LSEQ */

/* ---- output layout (flattened tuple, in reference return order) ---- */
static const size_t OUT_LOGITS = 0;
static const size_t OUT_X   = (size_t)NROWS * VOCAB;                 /* 61,440,000 */
static const size_t OUT_GSM = OUT_X   + (size_t)NROWS * DMODEL;      /* +2,097,152 */
static const size_t OUT_SSM = OUT_GSM + (size_t)NROWS * 4;
static const size_t OUT_GS  = OUT_SSM + (size_t)NROWS;
static const size_t OUT_SS  = OUT_GS  + (size_t)NLAY * NROWS * 4;

/* ---- scratch (no allocations allowed -> device globals) ---- */
__device__ float g_x  [NROWS * DMODEL];
__device__ float g_xm [NROWS * DMODEL];
__device__ float g_ain[NROWS * DMODEL];
__device__ float g_qkv[NROWS * 3 * DMODEL];
__device__ float g_pv [NROWS * NHEAD];
__device__ float g_ao [NROWS * DMODEL];
__device__ float g_ffh[NROWS * FFDIM];
__device__ float g_bndh[NROWS * HIDB];

/* ================= embedding + positional ================= */
__global__ void k_embed(const int* __restrict__ ids,
                        const float* __restrict__ emb,
                        const float* __restrict__ pos)
{
    int r = blockIdx.x;
    int l = r % LSEQ;
    int id = ids[r];
    const float4* e4 = (const float4*)(emb + (size_t)id * DMODEL);
    const float4* p4 = (const float4*)(pos + (size_t)l * DMODEL);
    float4* x4 = (float4*)(g_x + (size_t)r * DMODEL);
    for (int k = threadIdx.x; k < DMODEL / 4; k += blockDim.x) {
        float4 e = e4[k], p = p4[k];
        float4 o;
        o.x = e.x * 32.0f + p.x;
        o.y = e.y * 32.0f + p.y;
        o.z = e.z * 32.0f + p.z;
        o.w = e.w * 32.0f + p.w;
        x4[k] = o;
    }
}

/* ================= R-grammar gate + xm modulation ================= */
__global__ void k_rg_xm(const float* __restrict__ rg_w,
                        const float* __restrict__ rg_b,
                        int layer, float* __restrict__ gs_out)
{
    int r = blockIdx.x;
    int t = threadIdx.x;               /* 128 threads */
    const float* xr = g_x + (size_t)r * DMODEL;
    const float4* w4 = (const float4*)(rg_w + (size_t)layer * DMODEL * 4);
    float s0 = 0.f, s1 = 0.f, s2 = 0.f, s3 = 0.f;
    for (int k = t; k < DMODEL; k += 128) {
        float xv = xr[k];
        float4 w = w4[k];
        s0 += xv * w.x; s1 += xv * w.y; s2 += xv * w.z; s3 += xv * w.w;
    }
    for (int o = 16; o > 0; o >>= 1) {
        s0 += __shfl_down_sync(0xffffffffu, s0, o);
        s1 += __shfl_down_sync(0xffffffffu, s1, o);
        s2 += __shfl_down_sync(0xffffffffu, s2, o);
        s3 += __shfl_down_sync(0xffffffffu, s3, o);
    }
    __shared__ float red[4][4];
    __shared__ float mscale;
    int w = t >> 5, lane = t & 31;
    if (lane == 0) { red[w][0] = s0; red[w][1] = s1; red[w][2] = s2; red[w][3] = s3; }
    __syncthreads();
    if (t == 0) {
        float sum4 = 0.f;
        float* gsp = gs_out + ((size_t)layer * NROWS + r) * 4;
        #pragma unroll
        for (int n = 0; n < 4; n++) {
            float a = red[0][n] + red[1][n] + red[2][n] + red[3][n] + rg_b[layer * 4 + n];
            float sg = 1.0f / (1.0f + expf(-a));
            gsp[n] = sg;
            sum4 += sg;
        }
        mscale = 1.0f + 0.1f * (sum4 * 0.25f);
    }
    __syncthreads();
    float ms = mscale;
    const float4* x4 = (const float4*)xr;
    float4* xm4 = (float4*)(g_xm + (size_t)r * DMODEL);
    for (int k = t; k < DMODEL / 4; k += 128) {
        float4 v = x4[k];
        v.x *= ms; v.y *= ms; v.z *= ms; v.w *= ms;
        xm4[k] = v;
    }
}

/* ================= LayerNorm (block per row, 256 threads) ================= */
__global__ void k_ln(const float* __restrict__ in,
                     const float* __restrict__ g,
                     const float* __restrict__ b,
                     float* __restrict__ out)
{
    int r = blockIdx.x, t = threadIdx.x;  /* 256 threads, 1024 floats/row */
    const float4* i4 = (const float4*)(in + (size_t)r * DMODEL);
    float4 v = i4[t];
    float s = v.x + v.y + v.z + v.w;
    float q = v.x * v.x + v.y * v.y + v.z * v.z + v.w * v.w;
    for (int o = 16; o > 0; o >>= 1) {
        s += __shfl_down_sync(0xffffffffu, s, o);
        q += __shfl_down_sync(0xffffffffu, q, o);
    }
    __shared__ float sr[8], qr[8];
    __shared__ float smean, sinv;
    if ((t & 31) == 0) { sr[t >> 5] = s; qr[t >> 5] = q; }
    __syncthreads();
    if (t == 0) {
        float S = 0.f, Q = 0.f;
        #pragma unroll
        for (int i = 0; i < 8; i++) { S += sr[i]; Q += qr[i]; }
        float mean = S * (1.0f / DMODEL);
        float var = Q * (1.0f / DMODEL) - mean * mean;
        smean = mean;
        sinv = rsqrtf(var + 1e-5f);
    }
    __syncthreads();
    float mean = smean, inv = sinv;
    float4 gg = ((const float4*)g)[t];
    float4 bb = ((const float4*)b)[t];
    float4 o;
    o.x = (v.x - mean) * inv * gg.x + bb.x;
    o.y = (v.y - mean) * inv * gg.y + bb.y;
    o.z = (v.z - mean) * inv * gg.z + bb.z;
    o.w = (v.w - mean) * inv * gg.w + bb.w;
    ((float4*)(out + (size_t)r * DMODEL))[t] = o;
}

/* ================= GEMM: C = act(A@B + bias) (+ resid) =================
   A: [M,K] row-major.  TRANSB=0: B [K,N];  TRANSB=1: B [N,K] (C=A@B^T).
   act: 0 none, 1 exact GELU, 2 tanh. */
template <int TRANSB>
__global__ __launch_bounds__(256)
void k_gemm(const float* __restrict__ A, const float* __restrict__ Bm,
            const float* __restrict__ bias, const float* __restrict__ resid,
            float* __restrict__ C, int M, int N, int K, int act)
{
    const int BM = 128, BN = 64, BK = 16;
    __shared__ __align__(16) float As[BK][BM + 4];
    __shared__ __align__(16) float Bs[BK][BN];
    int tid = threadIdx.x;
    int m0 = blockIdx.y * BM, n0 = blockIdx.x * BN;
    int tr = tid >> 4;        /* 0..15 -> rows tr*8..tr*8+7 */
    int tc = tid & 15;        /* 0..15 -> cols tc*4..tc*4+3 */
    float acc[8][4];
    #pragma unroll
    for (int i = 0; i < 8; i++)
        #pragma unroll
        for (int j = 0; j < 4; j++) acc[i][j] = 0.f;

    for (int k0 = 0; k0 < K; k0 += BK) {
        /* A tile: 128x16 = 512 float4, 2 per thread */
        #pragma unroll
        for (int it = 0; it < 2; it++) {
            int i = tid + it * 256;
            int row = i >> 2;
            int kq = (i & 3) * 4;
            float4 v = *(const float4*)(A + (size_t)(m0 + row) * K + k0 + kq);
            As[kq + 0][row] = v.x;
            As[kq + 1][row] = v.y;
            As[kq + 2][row] = v.z;
            As[kq + 3][row] = v.w;
        }
        if (TRANSB == 0) {
            int row = tid >> 4;           /* k within tile */
            int col = (tid & 15) * 4;
            float4 v = *(const float4*)(Bm + (size_t)(k0 + row) * N + n0 + col);
            *(float4*)&Bs[row][col] = v;
        } else {
            int row = tid >> 2;           /* n within tile, 0..63 */
            int kq = (tid & 3) * 4;
            int n = n0 + row;
            float4 v = make_float4(0.f, 0.f, 0.f, 0.f);
            if (n < N) v = *(const float4*)(Bm + (size_t)n * K + k0 + kq);
            Bs[kq + 0][row] = v.x;
            Bs[kq + 1][row] = v.y;
            Bs[kq + 2][row] = v.z;
            Bs[kq + 3][row] = v.w;
        }
        __syncthreads();
        #pragma unroll
        for (int kk = 0; kk < BK; kk++) {
            float4 a0 = *(const float4*)&As[kk][tr * 8];
            float4 a1 = *(const float4*)&As[kk][tr * 8 + 4];
            float4 b0 = *(const float4*)&Bs[kk][tc * 4];
            float av[8] = {a0.x, a0.y, a0.z, a0.w, a1.x, a1.y, a1.z, a1.w};
            float bv[4] = {b0.x, b0.y, b0.z, b0.w};
            #pragma unroll
            for (int i = 0; i < 8; i++)
                #pragma unroll
                for (int j = 0; j < 4; j++)
                    acc[i][j] += av[i] * bv[j];
        }
        __syncthreads();
    }
    #pragma unroll
    for (int i = 0; i < 8; i++) {
        int row = m0 + tr * 8 + i;
        #pragma unroll
        for (int j = 0; j < 4; j++) {
            int col = n0 + tc * 4 + j;
            if (col < N) {
                float v = acc[i][j];
                if (bias) v += bias[col];
                if (act == 1)      v = 0.5f * v * (1.0f + erff(v * 0.70710678118654752f));
                else if (act == 2) v = tanhf(v);
                if (resid) v += resid[(size_t)row * N + col];
                C[(size_t)row * N + col] = v;
            }
        }
    }
}

/* ================= phase vector: pv = tanh(ps*(a_in@ph_w + ph_b)) ================= */
__global__ void k_ph(const float* __restrict__ ph_w,
                     const float* __restrict__ ph_b,
                     const float* __restrict__ ph_scale, int layer)
{
    int r = blockIdx.x, t = threadIdx.x;   /* 128 threads */
    const float* ar = g_ain + (size_t)r * DMODEL;
    const float4* w4 = (const float4*)(ph_w + (size_t)layer * DMODEL * NHEAD);
    float acc[16];
    #pragma unroll
    for (int n = 0; n < 16; n++) acc[n] = 0.f;
    for (int k = t; k < DMODEL; k += 128) {
        float a = ar[k];
        #pragma unroll
        for (int q = 0; q < 4; q++) {
            float4 w = w4[k * 4 + q];
            acc[q * 4 + 0] += a * w.x;
            acc[q * 4 + 1] += a * w.y;
            acc[q * 4 + 2] += a * w.z;
            acc[q * 4 + 3] += a * w.w;
        }
    }
    __shared__ float red[128][16];
    #pragma unroll
    for (int n = 0; n < 16; n++) red[t][n] = acc[n];
    __syncthreads();
    for (int s = 64; s >= 1; s >>= 1) {
        if (t < s) {
            #pragma unroll
            for (int n = 0; n < 16; n++) red[t][n] += red[t + s][n];
        }
        __syncthreads();
    }
    if (t < 16) {
        float v = red[0][t] + ph_b[layer * NHEAD + t];
        g_pv[(size_t)r * NHEAD + t] = tanhf(ph_scale[layer] * v);
    }
}

/* ================= fused attention (online softmax + phase penalty) ================= */
__global__ __launch_bounds__(128)
void k_attn(const float* __restrict__ res_scale, int layer)
{
    int b = blockIdx.z, h = blockIdx.y, rb = blockIdx.x;
    int t = threadIdx.x;
    int l = rb * 128 + t;                      /* query row within seq */
    float rs = res_scale[layer];

    __shared__ float4 Ks4[32 * 16];
    __shared__ float4 Vs4[32 * 16];
    __shared__ float  pvs[32];

    const float* qptr = g_qkv + ((size_t)(b * LSEQ + l) * 3 * DMODEL) + h * DHEAD;
    float4 q4[16];
    #pragma unroll
    for (int i = 0; i < 16; i++) q4[i] = ((const float4*)qptr)[i];
    float pvq = g_pv[(size_t)(b * LSEQ + l) * NHEAD + h];

    float4 o4[16];
    #pragma unroll
    for (int i = 0; i < 16; i++) o4[i] = make_float4(0.f, 0.f, 0.f, 0.f);
    float mrun = -1e30f, denom = 0.f;

    for (int m0 = 0; m0 < LSEQ; m0 += 32) {
        for (int i = t; i < 512; i += 128) {
            int row = i >> 4, f = i & 15;
            const float* kp = g_qkv + ((size_t)(b * LSEQ + m0 + row) * 3 * DMODEL) + DMODEL + h * DHEAD;
            Ks4[row * 16 + f] = ((const float4*)kp)[f];
            Vs4[row * 16 + f] = ((const float4*)(kp + DMODEL))[f];
        }
        if (t < 32) pvs[t] = g_pv[(size_t)(b * LSEQ + m0 + t) * NHEAD + h];
        __syncthreads();

        float s[32];
        float tmax = -1e30f;
        #pragma unroll
        for (int j = 0; j < 32; j++) {
            float sj = 0.f;
            #pragma unroll
            for (int i = 0; i < 16; i++) {
                float4 kv = Ks4[j * 16 + i];
                sj += q4[i].x * kv.x + q4[i].y * kv.y + q4[i].z * kv.z + q4[i].w * kv.w;
            }
            float dp = pvq - pvs[j];
            sj = sj * 0.125f - rs * dp * dp;
            s[j] = sj;
            tmax = fmaxf(tmax, sj);
        }
        float mnew = fmaxf(mrun, tmax);
        float corr = expf(mrun - mnew);
        denom *= corr;
        #pragma unroll
        for (int i = 0; i < 16; i++) {
            o4[i].x *= corr; o4[i].y *= corr; o4[i].z *= corr; o4[i].w *= corr;
        }
        #pragma unroll
        for (int j = 0; j < 32; j++) {
            float p = expf(s[j] - mnew);
            denom += p;
            #pragma unroll
            for (int i = 0; i < 16; i++) {
                float4 vv = Vs4[j * 16 + i];
                o4[i].x += p * vv.x; o4[i].y += p * vv.y;
                o4[i].z += p * vv.z; o4[i].w += p * vv.w;
            }
        }
        mrun = mnew;
        __syncthreads();
    }
    float inv = 1.0f / denom;
    float4* op = (float4*)(g_ao + (size_t)(b * LSEQ + l) * DMODEL + h * DHEAD);
    #pragma unroll
    for (int i = 0; i < 16; i++) {
        float4 o = o4[i];
        o.x *= inv; o.y *= inv; o.z *= inv; o.w *= inv;
        op[i] = o;
    }
}

/* ================= boundary scalar: sigmoid(bndh @ w2 + b2) ================= */
__global__ void k_bnd2(const float* __restrict__ w2,
                       const float* __restrict__ b2,
                       float* __restrict__ ss_out, int layer)
{
    int r = blockIdx.x, t = threadIdx.x;   /* 128 threads */
    const float* hr = g_bndh + (size_t)r * HIDB;
    float s = 0.f;
    for (int k = t; k < HIDB; k += 128) s += hr[k] * w2[k];
    for (int o = 16; o > 0; o >>= 1) s += __shfl_down_sync(0xffffffffu, s, o);
    __shared__ float red[4];
    if ((t & 31) == 0) red[t >> 5] = s;
    __syncthreads();
    if (t == 0) {
        float v = red[0] + red[1] + red[2] + red[3] + b2[0];
        ss_out[(size_t)layer * NROWS + r] = 1.0f / (1.0f + expf(-v));
    }
}

/* ================= means over layers ================= */
__global__ void k_means(float* out)
{
    int idx = blockIdx.x * 256 + threadIdx.x;
    if (idx < NROWS * 4) {
        float s = 0.f;
        #pragma unroll
        for (int l = 0; l < NLAY; l++) s += out[OUT_GS + (size_t)l * NROWS * 4 + idx];
        out[OUT_GSM + idx] = s * (1.0f / NLAY);
    }
    int idx2 = idx - NROWS * 4;
    if (idx2 >= 0 && idx2 < NROWS) {
        float s = 0.f;
        #pragma unroll
        for (int l = 0; l < NLAY; l++) s += out[OUT_SS + (size_t)l * NROWS + idx2];
        out[OUT_SSM + idx2] = s * (1.0f / NLAY);
    }
}

/* ================= host ================= */
extern "C" void kernel_launch(void* const* d_in, const int* in_sizes, int n_in,
                              void* d_out, int out_size)
{
    const int*   ids      = (const int*)  d_in[0];
    const float* embed    = (const float*)d_in[1];
    const float* pos_enc  = (const float*)d_in[2];
    const float* rg_w     = (const float*)d_in[3];
    const float* rg_b     = (const float*)d_in[4];
    const float* qkv_w    = (const float*)d_in[5];
    const float* qkv_b    = (const float*)d_in[6];
    const float* out_w    = (const float*)d_in[7];
    const float* out_b    = (const float*)d_in[8];
    const float* ph_w     = (const float*)d_in[9];
    const float* ph_b     = (const float*)d_in[10];
    const float* resscale = (const float*)d_in[11];
    const float* ph_scale = (const float*)d_in[12];
    const float* ff1_w    = (const float*)d_in[13];
    const float* ff1_b    = (const float*)d_in[14];
    const float* ff2_w    = (const float*)d_in[15];
    const float* ff2_b    = (const float*)d_in[16];
    const float* n1_g     = (const float*)d_in[17];
    const float* n1_b     = (const float*)d_in[18];
    const float* n2_g     = (const float*)d_in[19];
    const float* n2_b     = (const float*)d_in[20];
    const float* bnd_w1   = (const float*)d_in[21];
    const float* bnd_b1   = (const float*)d_in[22];
    const float* bnd_w2   = (const float*)d_in[23];
    const float* bnd_b2   = (const float*)d_in[24];
    const float* fn_g     = (const float*)d_in[25];
    const float* fn_b     = (const float*)d_in[26];
    float* out = (float*)d_out;

    float *px, *pxm, *pain, *pqkv, *pao, *pffh, *pbndh;
    cudaGetSymbolAddress((void**)&px,    g_x);
    cudaGetSymbolAddress((void**)&pxm,   g_xm);
    cudaGetSymbolAddress((void**)&pain,  g_ain);
    cudaGetSymbolAddress((void**)&pqkv,  g_qkv);
    cudaGetSymbolAddress((void**)&pao,   g_ao);
    cudaGetSymbolAddress((void**)&pffh,  g_ffh);
    cudaGetSymbolAddress((void**)&pbndh, g_bndh);

    k_embed<<<NROWS, 256>>>(ids, embed, pos_enc);

    for (int i = 0; i < NLAY; i++) {
        /* gate + modulation */
        k_rg_xm<<<NROWS, 128>>>(rg_w, rg_b, i, out + OUT_GS);
        /* pre-norm 1 */
        k_ln<<<NROWS, 256>>>(pxm, n1_g + (size_t)i * DMODEL, n1_b + (size_t)i * DMODEL, pain);
        /* QKV projection */
        {
            dim3 grid((3 * DMODEL) / 64, NROWS / 128);
            k_gemm<0><<<grid, 256>>>(pain, qkv_w + (size_t)i * DMODEL * 3 * DMODEL,
                                     qkv_b + (size_t)i * 3 * DMODEL, nullptr,
                                     pqkv, NROWS, 3 * DMODEL, DMODEL, 0);
        }
        /* phase vector */
        k_ph<<<NROWS, 128>>>(ph_w, ph_b, ph_scale, i);
        /* fused attention */
        {
            dim3 grid(LSEQ / 128, NHEAD, NB);
            k_attn<<<grid, 128>>>(resscale, i);
        }
        /* out projection + residual (xm) */
        {
            dim3 grid(DMODEL / 64, NROWS / 128);
            k_gemm<0><<<grid, 256>>>(pao, out_w + (size_t)i * DMODEL * DMODEL,
                                     out_b + (size_t)i * DMODEL, pxm,
                                     px, NROWS, DMODEL, DMODEL, 0);
        }
        /* pre-norm 2 */
        k_ln<<<NROWS, 256>>>(px, n2_g + (size_t)i * DMODEL, n2_b + (size_t)i * DMODEL, pain);
        /* FF1 with exact GELU */
        {
            dim3 grid(FFDIM / 64, NROWS / 128);
            k_gemm<0><<<grid, 256>>>(pain, ff1_w + (size_t)i * DMODEL * FFDIM,
                                     ff1_b + (size_t)i * FFDIM, nullptr,
                                     pffh, NROWS, FFDIM, DMODEL, 1);
        }
        /* FF2 + residual (x) */
        {
            dim3 grid(DMODEL / 64, NROWS / 128);
            k_gemm<0><<<grid, 256>>>(pffh, ff2_w + (size_t)i * FFDIM * DMODEL,
                                     ff2_b + (size_t)i * DMODEL, px,
                                     px, NROWS, DMODEL, FFDIM, 0);
        }
        /* boundary MLP */
        {
            dim3 grid(HIDB / 64, NROWS / 128);
            k_gemm<0><<<grid, 256>>>(px, bnd_w1, bnd_b1, nullptr,
                                     pbndh, NROWS, HIDB, DMODEL, 2);
        }
        k_bnd2<<<NROWS, 128>>>(bnd_w2, bnd_b2, out + OUT_SS, i);
    }

    /* final LN -> output x region (also GEMM input) */
    k_ln<<<NROWS, 256>>>(px, fn_g, fn_b, out + OUT_X);

    /* logits = x @ embed^T */
    {
        dim3 grid((VOCAB + 63) / 64, NROWS / 128);
        k_gemm<1><<<grid, 256>>>(out + OUT_X, embed, nullptr, nullptr,
                                 out + OUT_LOGITS, NROWS, VOCAB, DMODEL, 0);
    }

    /* layer means */
    k_means<<<(NROWS * 4 + NROWS + 255) / 256, 256>>>(out);
}

// round 3
// speedup vs baseline: 2.3358x; 2.3358x over previous
#include <cuda_runtime.h>
#include <math.h>
#include <stdint.h>

#define NB      2
#define LSEQ    1024
#define DMODEL  1024
#define NHEAD   16
#define DHEAD   64
#define NLAY    6
#define VOCAB   30000
#define VPAD    30080
#define HIDB    512
#define FFDIM   4096
#define NROWS   2048   /* NB*LSEQ */

/* ---- output layout (flattened tuple, in reference return order) ---- */
static const size_t OUT_LOGITS = 0;
static const size_t OUT_X   = (size_t)NROWS * VOCAB;
static const size_t OUT_GSM = OUT_X   + (size_t)NROWS * DMODEL;
static const size_t OUT_SSM = OUT_GSM + (size_t)NROWS * 4;
static const size_t OUT_GS  = OUT_SSM + (size_t)NROWS;
static const size_t OUT_SS  = OUT_GS  + (size_t)NLAY * NROWS * 4;

/* ---- scratch ---- */
__device__ float g_x  [NROWS * DMODEL];
__device__ float g_xm [NROWS * DMODEL];
__device__ float g_ain[NROWS * DMODEL];
__device__ float g_qkv[NROWS * 3 * DMODEL];
__device__ float g_pv [NROWS * NHEAD];
__device__ float g_ao [NROWS * DMODEL];
__device__ float g_ffh[NROWS * FFDIM];
__device__ float g_bndh[NROWS * HIDB];
__device__ float g_embT[(size_t)DMODEL * VPAD];   /* embed^T, padded cols */

/* ================= low-level helpers (compute_103-safe) ================= */
__device__ __forceinline__ uint32_t smem_u32(const void* p) {
    uint32_t a;
    asm("{ .reg .u64 t; cvta.to.shared.u64 t, %1; cvt.u32.u64 %0, t; }" : "=r"(a) : "l"(p));
    return a;
}
__device__ __forceinline__ void cp16(void* s, const void* g) {
    asm volatile("cp.async.cg.shared.global [%0], [%1], 16;"
                 :: "r"(smem_u32(s)), "l"(g) : "memory");
}
#define CP_COMMIT() asm volatile("cp.async.commit_group;" ::: "memory")
#define CP_WAIT1()  asm volatile("cp.async.wait_group 1;" ::: "memory")
#define CP_WAIT0()  asm volatile("cp.async.wait_group 0;" ::: "memory")

__device__ __forceinline__ uint32_t cvt_tf32(float f) {
    uint32_t r;
    asm("cvt.rna.tf32.f32 %0, %1;" : "=r"(r) : "f"(f));
    return r;
}
__device__ __forceinline__ void mma_m16n8k8(float* c, const uint32_t* a, const uint32_t* b) {
    asm volatile(
        "mma.sync.aligned.m16n8k8.row.col.f32.tf32.tf32.f32 "
        "{%0,%1,%2,%3}, {%4,%5,%6,%7}, {%8,%9}, {%0,%1,%2,%3};"
        : "+f"(c[0]), "+f"(c[1]), "+f"(c[2]), "+f"(c[3])
        : "r"(a[0]), "r"(a[1]), "r"(a[2]), "r"(a[3]), "r"(b[0]), "r"(b[1]));
}

/* ================= tf32 mma GEMM =================
   C[M,N] = act(A[M,K] @ B[K,N] + bias) (+resid); B row length = ldb.
   act: 0 none, 1 exact GELU, 2 tanh.
   SMEM: A stage [128][32] with 16B-chunk XOR swizzle; B stage [32][128]
   with word-index XOR ((row&3)*8). Double-buffered cp.async pipeline. */
__global__ __launch_bounds__(256)
void k_mma_gemm(const float* __restrict__ A, const float* __restrict__ Bm,
                const float* __restrict__ bias, const float* __restrict__ resid,
                float* __restrict__ C, int M, int N, int K, int ldb, int act)
{
    extern __shared__ float smem[];
    float* As = smem;              /* 2 stages x 4096 floats */
    float* Bs = smem + 2 * 4096;   /* 2 stages x 4096 floats */

    const int tid  = threadIdx.x;
    const int wid  = tid >> 5;
    const int lane = tid & 31;
    const int m0 = blockIdx.y * 128;
    const int n0 = blockIdx.x * 128;
    const int wm = (wid & 1) * 64;
    const int wn = (wid >> 1) * 32;
    const int nch = K / 32;

    const int a_row = tid >> 3, a_c4 = tid & 7;       /* A staging coords */
    const int b_kr  = tid >> 5, b_c4 = tid & 31;      /* B staging coords */
    const uint32_t a_dst = (uint32_t)a_row * 32u + (uint32_t)((a_c4 ^ (a_row & 7)) * 4);
    const uint32_t b_dst = (uint32_t)b_kr * 128u + (uint32_t)((b_c4 * 4) ^ ((b_kr & 3) * 8));
    const float* a_src0 = A + (size_t)(m0 + a_row) * K + a_c4 * 4;
    const float* b_src0 = Bm + (size_t)b_kr * ldb + n0 + b_c4 * 4;

    /* stage chunk c into buffer s */
    #define STAGE(c, s) do {                                                   \
        float* as = As + (s) * 4096;                                           \
        float* bs = Bs + (s) * 4096;                                           \
        const float* ap = a_src0 + (c) * 32;                                   \
        const float* bp = b_src0 + (size_t)(c) * 32 * ldb;                     \
        _Pragma("unroll")                                                      \
        for (int it = 0; it < 4; it++)                                         \
            cp16(as + a_dst + it * (32 * 32), ap + (size_t)(it * 32) * K);     \
        _Pragma("unroll")                                                      \
        for (int it = 0; it < 4; it++)                                         \
            cp16(bs + b_dst + it * (8 * 128), bp + (size_t)(it * 8) * ldb);    \
    } while (0)

    float cf[4][4][4];
    #pragma unroll
    for (int i = 0; i < 4; i++)
        #pragma unroll
        for (int j = 0; j < 4; j++)
            { cf[i][j][0] = 0.f; cf[i][j][1] = 0.f; cf[i][j][2] = 0.f; cf[i][j][3] = 0.f; }

    STAGE(0, 0);
    CP_COMMIT();

    const int fa_r  = lane >> 2;    /* group id */
    const int fa_t  = lane & 3;

    for (int c = 0; c < nch; c++) {
        if (c + 1 < nch) { STAGE(c + 1, (c + 1) & 1); CP_COMMIT(); CP_WAIT1(); }
        else             { CP_WAIT0(); }
        __syncthreads();

        const float* as = As + (c & 1) * 4096;
        const float* bs = Bs + (c & 1) * 4096;

        #pragma unroll
        for (int kk = 0; kk < 4; kk++) {
            const int k = kk * 8;
            uint32_t af[4][4];
            #pragma unroll
            for (int mt = 0; mt < 4; mt++) {
                int r = wm + mt * 16 + fa_r;
                int col0 = k + fa_t;
                int col1 = col0 + 4;
                /* word = r*32 + ((col>>2 ^ (r&7))*4 + (col&3)) */
                uint32_t base = (uint32_t)r * 32u;
                uint32_t sw = (uint32_t)(r & 7);
                af[mt][0] = cvt_tf32(as[base + ((((uint32_t)col0 >> 2) ^ sw) * 4u) + (col0 & 3)]);
                af[mt][2] = cvt_tf32(as[base + ((((uint32_t)col1 >> 2) ^ sw) * 4u) + (col1 & 3)]);
                uint32_t base8 = base + 8u * 32u;
                af[mt][1] = cvt_tf32(as[base8 + ((((uint32_t)col0 >> 2) ^ sw) * 4u) + (col0 & 3)]);
                af[mt][3] = cvt_tf32(as[base8 + ((((uint32_t)col1 >> 2) ^ sw) * 4u) + (col1 & 3)]);
            }
            uint32_t bf[4][2];
            #pragma unroll
            for (int nt = 0; nt < 4; nt++) {
                int n = wn + nt * 8 + fa_r;
                int r0 = k + fa_t;
                int r1 = r0 + 4;
                bf[nt][0] = cvt_tf32(bs[(uint32_t)r0 * 128u + ((uint32_t)n ^ (uint32_t)((r0 & 3) * 8))]);
                bf[nt][1] = cvt_tf32(bs[(uint32_t)r1 * 128u + ((uint32_t)n ^ (uint32_t)((r1 & 3) * 8))]);
            }
            #pragma unroll
            for (int mt = 0; mt < 4; mt++)
                #pragma unroll
                for (int nt = 0; nt < 4; nt++)
                    mma_m16n8k8(cf[mt][nt], af[mt], bf[nt]);
        }
        __syncthreads();
    }
    #undef STAGE

    /* epilogue: c0,c1 at (row, col..col+1); c2,c3 at (row+8, ...) */
    #pragma unroll
    for (int mt = 0; mt < 4; mt++) {
        int row = m0 + wm + mt * 16 + (lane >> 2);
        #pragma unroll
        for (int nt = 0; nt < 4; nt++) {
            int col = n0 + wn + nt * 8 + (lane & 3) * 2;
            if (col < N) {
                #pragma unroll
                for (int half = 0; half < 2; half++) {
                    int r = row + half * 8;
                    float v0 = cf[mt][nt][half * 2 + 0];
                    float v1 = cf[mt][nt][half * 2 + 1];
                    if (bias) { v0 += bias[col]; v1 += bias[col + 1]; }
                    if (act == 1) {
                        v0 = 0.5f * v0 * (1.0f + erff(v0 * 0.70710678118654752f));
                        v1 = 0.5f * v1 * (1.0f + erff(v1 * 0.70710678118654752f));
                    } else if (act == 2) {
                        v0 = tanhf(v0); v1 = tanhf(v1);
                    }
                    if (resid) {
                        v0 += resid[(size_t)r * N + col];
                        v1 += resid[(size_t)r * N + col + 1];
                    }
                    float2 o = make_float2(v0, v1);
                    *(float2*)(C + (size_t)r * N + col) = o;
                }
            }
        }
    }
}

/* ================= embed transpose: g_embT[d][v] = embed[v][d] ================= */
__global__ void k_transpose(const float* __restrict__ in)
{
    __shared__ float t[32][33];
    int v0 = blockIdx.x * 32, d0 = blockIdx.y * 32;
    int tx = threadIdx.x, ty = threadIdx.y;     /* 32 x 8 */
    #pragma unroll
    for (int i = 0; i < 4; i++) {
        int v = v0 + ty + i * 8;
        if (v < VOCAB) t[ty + i * 8][tx] = in[(size_t)v * DMODEL + d0 + tx];
    }
    __syncthreads();
    #pragma unroll
    for (int i = 0; i < 4; i++) {
        int v = v0 + tx;
        if (v < VOCAB)
            g_embT[(size_t)(d0 + ty + i * 8) * VPAD + v] = t[tx][ty + i * 8];
    }
}

/* ================= embedding + positional ================= */
__global__ void k_embed(const int* __restrict__ ids,
                        const float* __restrict__ emb,
                        const float* __restrict__ pos)
{
    int r = blockIdx.x;
    int l = r % LSEQ;
    int id = ids[r];
    const float4* e4 = (const float4*)(emb + (size_t)id * DMODEL);
    const float4* p4 = (const float4*)(pos + (size_t)l * DMODEL);
    float4* x4 = (float4*)(g_x + (size_t)r * DMODEL);
    for (int k = threadIdx.x; k < DMODEL / 4; k += blockDim.x) {
        float4 e = e4[k], p = p4[k];
        float4 o;
        o.x = e.x * 32.0f + p.x;
        o.y = e.y * 32.0f + p.y;
        o.z = e.z * 32.0f + p.z;
        o.w = e.w * 32.0f + p.w;
        x4[k] = o;
    }
}

/* ================= R-grammar gate + xm modulation ================= */
__global__ void k_rg_xm(const float* __restrict__ rg_w,
                        const float* __restrict__ rg_b,
                        int layer, float* __restrict__ gs_out)
{
    int r = blockIdx.x;
    int t = threadIdx.x;               /* 128 threads */
    const float* xr = g_x + (size_t)r * DMODEL;
    const float4* w4 = (const float4*)(rg_w + (size_t)layer * DMODEL * 4);
    float s0 = 0.f, s1 = 0.f, s2 = 0.f, s3 = 0.f;
    for (int k = t; k < DMODEL; k += 128) {
        float xv = xr[k];
        float4 w = w4[k];
        s0 += xv * w.x; s1 += xv * w.y; s2 += xv * w.z; s3 += xv * w.w;
    }
    for (int o = 16; o > 0; o >>= 1) {
        s0 += __shfl_down_sync(0xffffffffu, s0, o);
        s1 += __shfl_down_sync(0xffffffffu, s1, o);
        s2 += __shfl_down_sync(0xffffffffu, s2, o);
        s3 += __shfl_down_sync(0xffffffffu, s3, o);
    }
    __shared__ float red[4][4];
    __shared__ float mscale;
    int w = t >> 5, lane = t & 31;
    if (lane == 0) { red[w][0] = s0; red[w][1] = s1; red[w][2] = s2; red[w][3] = s3; }
    __syncthreads();
    if (t == 0) {
        float sum4 = 0.f;
        float* gsp = gs_out + ((size_t)layer * NROWS + r) * 4;
        #pragma unroll
        for (int n = 0; n < 4; n++) {
            float a = red[0][n] + red[1][n] + red[2][n] + red[3][n] + rg_b[layer * 4 + n];
            float sg = 1.0f / (1.0f + expf(-a));
            gsp[n] = sg;
            sum4 += sg;
        }
        mscale = 1.0f + 0.1f * (sum4 * 0.25f);
    }
    __syncthreads();
    float ms = mscale;
    const float4* x4 = (const float4*)xr;
    float4* xm4 = (float4*)(g_xm + (size_t)r * DMODEL);
    for (int k = t; k < DMODEL / 4; k += 128) {
        float4 v = x4[k];
        v.x *= ms; v.y *= ms; v.z *= ms; v.w *= ms;
        xm4[k] = v;
    }
}

/* ================= LayerNorm ================= */
__global__ void k_ln(const float* __restrict__ in,
                     const float* __restrict__ g,
                     const float* __restrict__ b,
                     float* __restrict__ out)
{
    int r = blockIdx.x, t = threadIdx.x;  /* 256 threads, 1024 floats/row */
    const float4* i4 = (const float4*)(in + (size_t)r * DMODEL);
    float4 v = i4[t];
    float s = v.x + v.y + v.z + v.w;
    float q = v.x * v.x + v.y * v.y + v.z * v.z + v.w * v.w;
    for (int o = 16; o > 0; o >>= 1) {
        s += __shfl_down_sync(0xffffffffu, s, o);
        q += __shfl_down_sync(0xffffffffu, q, o);
    }
    __shared__ float sr[8], qr[8];
    __shared__ float smean, sinv;
    if ((t & 31) == 0) { sr[t >> 5] = s; qr[t >> 5] = q; }
    __syncthreads();
    if (t == 0) {
        float S = 0.f, Q = 0.f;
        #pragma unroll
        for (int i = 0; i < 8; i++) { S += sr[i]; Q += qr[i]; }
        float mean = S * (1.0f / DMODEL);
        float var = Q * (1.0f / DMODEL) - mean * mean;
        smean = mean;
        sinv = rsqrtf(var + 1e-5f);
    }
    __syncthreads();
    float mean = smean, inv = sinv;
    float4 gg = ((const float4*)g)[t];
    float4 bb = ((const float4*)b)[t];
    float4 o;
    o.x = (v.x - mean) * inv * gg.x + bb.x;
    o.y = (v.y - mean) * inv * gg.y + bb.y;
    o.z = (v.z - mean) * inv * gg.z + bb.z;
    o.w = (v.w - mean) * inv * gg.w + bb.w;
    ((float4*)(out + (size_t)r * DMODEL))[t] = o;
}

/* ================= phase vector ================= */
__global__ void k_ph(const float* __restrict__ ph_w,
                     const float* __restrict__ ph_b,
                     const float* __restrict__ ph_scale, int layer)
{
    int r = blockIdx.x, t = threadIdx.x;   /* 128 threads */
    const float* ar = g_ain + (size_t)r * DMODEL;
    const float4* w4 = (const float4*)(ph_w + (size_t)layer * DMODEL * NHEAD);
    float acc[16];
    #pragma unroll
    for (int n = 0; n < 16; n++) acc[n] = 0.f;
    for (int k = t; k < DMODEL; k += 128) {
        float a = ar[k];
        #pragma unroll
        for (int q = 0; q < 4; q++) {
            float4 w = w4[k * 4 + q];
            acc[q * 4 + 0] += a * w.x;
            acc[q * 4 + 1] += a * w.y;
            acc[q * 4 + 2] += a * w.z;
            acc[q * 4 + 3] += a * w.w;
        }
    }
    __shared__ float red[128][16];
    #pragma unroll
    for (int n = 0; n < 16; n++) red[t][n] = acc[n];
    __syncthreads();
    for (int s = 64; s >= 1; s >>= 1) {
        if (t < s) {
            #pragma unroll
            for (int n = 0; n < 16; n++) red[t][n] += red[t + s][n];
        }
        __syncthreads();
    }
    if (t < 16) {
        float v = red[0][t] + ph_b[layer * NHEAD + t];
        g_pv[(size_t)r * NHEAD + t] = tanhf(ph_scale[layer] * v);
    }
}

/* ================= fused attention ================= */
__global__ __launch_bounds__(128)
void k_attn(const float* __restrict__ res_scale, int layer)
{
    int b = blockIdx.z, h = blockIdx.y, rb = blockIdx.x;
    int t = threadIdx.x;
    int l = rb * 128 + t;
    float rs = res_scale[layer];

    __shared__ float4 Ks4[32 * 16];
    __shared__ float4 Vs4[32 * 16];
    __shared__ float  pvs[32];

    const float* qptr = g_qkv + ((size_t)(b * LSEQ + l) * 3 * DMODEL) + h * DHEAD;
    float4 q4[16];
    #pragma unroll
    for (int i = 0; i < 16; i++) q4[i] = ((const float4*)qptr)[i];
    float pvq = g_pv[(size_t)(b * LSEQ + l) * NHEAD + h];

    float4 o4[16];
    #pragma unroll
    for (int i = 0; i < 16; i++) o4[i] = make_float4(0.f, 0.f, 0.f, 0.f);
    float mrun = -1e30f, denom = 0.f;

    for (int m0 = 0; m0 < LSEQ; m0 += 32) {
        for (int i = t; i < 512; i += 128) {
            int row = i >> 4, f = i & 15;
            const float* kp = g_qkv + ((size_t)(b * LSEQ + m0 + row) * 3 * DMODEL) + DMODEL + h * DHEAD;
            Ks4[row * 16 + f] = ((const float4*)kp)[f];
            Vs4[row * 16 + f] = ((const float4*)(kp + DMODEL))[f];
        }
        if (t < 32) pvs[t] = g_pv[(size_t)(b * LSEQ + m0 + t) * NHEAD + h];
        __syncthreads();

        float s[32];
        float tmax = -1e30f;
        #pragma unroll
        for (int j = 0; j < 32; j++) {
            float sj = 0.f;
            #pragma unroll
            for (int i = 0; i < 16; i++) {
                float4 kv = Ks4[j * 16 + i];
                sj += q4[i].x * kv.x + q4[i].y * kv.y + q4[i].z * kv.z + q4[i].w * kv.w;
            }
            float dp = pvq - pvs[j];
            sj = sj * 0.125f - rs * dp * dp;
            s[j] = sj;
            tmax = fmaxf(tmax, sj);
        }
        float mnew = fmaxf(mrun, tmax);
        float corr = expf(mrun - mnew);
        denom *= corr;
        #pragma unroll
        for (int i = 0; i < 16; i++) {
            o4[i].x *= corr; o4[i].y *= corr; o4[i].z *= corr; o4[i].w *= corr;
        }
        #pragma unroll
        for (int j = 0; j < 32; j++) {
            float p = expf(s[j] - mnew);
            denom += p;
            #pragma unroll
            for (int i = 0; i < 16; i++) {
                float4 vv = Vs4[j * 16 + i];
                o4[i].x += p * vv.x; o4[i].y += p * vv.y;
                o4[i].z += p * vv.z; o4[i].w += p * vv.w;
            }
        }
        mrun = mnew;
        __syncthreads();
    }
    float inv = 1.0f / denom;
    float4* op = (float4*)(g_ao + (size_t)(b * LSEQ + l) * DMODEL + h * DHEAD);
    #pragma unroll
    for (int i = 0; i < 16; i++) {
        float4 o = o4[i];
        o.x *= inv; o.y *= inv; o.z *= inv; o.w *= inv;
        op[i] = o;
    }
}

/* ================= boundary scalar ================= */
__global__ void k_bnd2(const float* __restrict__ w2,
                       const float* __restrict__ b2,
                       float* __restrict__ ss_out, int layer)
{
    int r = blockIdx.x, t = threadIdx.x;   /* 128 threads */
    const float* hr = g_bndh + (size_t)r * HIDB;
    float s = 0.f;
    for (int k = t; k < HIDB; k += 128) s += hr[k] * w2[k];
    for (int o = 16; o > 0; o >>= 1) s += __shfl_down_sync(0xffffffffu, s, o);
    __shared__ float red[4];
    if ((t & 31) == 0) red[t >> 5] = s;
    __syncthreads();
    if (t == 0) {
        float v = red[0] + red[1] + red[2] + red[3] + b2[0];
        ss_out[(size_t)layer * NROWS + r] = 1.0f / (1.0f + expf(-v));
    }
}

/* ================= means over layers ================= */
__global__ void k_means(float* out)
{
    int idx = blockIdx.x * 256 + threadIdx.x;
    if (idx < NROWS * 4) {
        float s = 0.f;
        #pragma unroll
        for (int l = 0; l < NLAY; l++) s += out[OUT_GS + (size_t)l * NROWS * 4 + idx];
        out[OUT_GSM + idx] = s * (1.0f / NLAY);
    }
    int idx2 = idx - NROWS * 4;
    if (idx2 >= 0 && idx2 < NROWS) {
        float s = 0.f;
        #pragma unroll
        for (int l = 0; l < NLAY; l++) s += out[OUT_SS + (size_t)l * NROWS + idx2];
        out[OUT_SSM + idx2] = s * (1.0f / NLAY);
    }
}

/* ================= host ================= */
#define GEMM_SMEM (4 * 4096 * 4)   /* 64 KB */

extern "C" void kernel_launch(void* const* d_in, const int* in_sizes, int n_in,
                              void* d_out, int out_size)
{
    const int*   ids      = (const int*)  d_in[0];
    const float* embed    = (const float*)d_in[1];
    const float* pos_enc  = (const float*)d_in[2];
    const float* rg_w     = (const float*)d_in[3];
    const float* rg_b     = (const float*)d_in[4];
    const float* qkv_w    = (const float*)d_in[5];
    const float* qkv_b    = (const float*)d_in[6];
    const float* out_w    = (const float*)d_in[7];
    const float* out_b    = (const float*)d_in[8];
    const float* ph_w     = (const float*)d_in[9];
    const float* ph_b     = (const float*)d_in[10];
    const float* resscale = (const float*)d_in[11];
    const float* ph_scale = (const float*)d_in[12];
    const float* ff1_w    = (const float*)d_in[13];
    const float* ff1_b    = (const float*)d_in[14];
    const float* ff2_w    = (const float*)d_in[15];
    const float* ff2_b    = (const float*)d_in[16];
    const float* n1_g     = (const float*)d_in[17];
    const float* n1_b     = (const float*)d_in[18];
    const float* n2_g     = (const float*)d_in[19];
    const float* n2_b     = (const float*)d_in[20];
    const float* bnd_w1   = (const float*)d_in[21];
    const float* bnd_b1   = (const float*)d_in[22];
    const float* bnd_w2   = (const float*)d_in[23];
    const float* bnd_b2   = (const float*)d_in[24];
    const float* fn_g     = (const float*)d_in[25];
    const float* fn_b     = (const float*)d_in[26];
    float* out = (float*)d_out;

    float *px, *pxm, *pain, *pqkv, *pao, *pffh, *pbndh, *pembT;
    cudaGetSymbolAddress((void**)&px,    g_x);
    cudaGetSymbolAddress((void**)&pxm,   g_xm);
    cudaGetSymbolAddress((void**)&pain,  g_ain);
    cudaGetSymbolAddress((void**)&pqkv,  g_qkv);
    cudaGetSymbolAddress((void**)&pao,   g_ao);
    cudaGetSymbolAddress((void**)&pffh,  g_ffh);
    cudaGetSymbolAddress((void**)&pbndh, g_bndh);
    cudaGetSymbolAddress((void**)&pembT, g_embT);

    cudaFuncSetAttribute(k_mma_gemm, cudaFuncAttributeMaxDynamicSharedMemorySize, GEMM_SMEM);

    /* embed^T for the logits GEMM */
    {
        dim3 grid((VOCAB + 31) / 32, DMODEL / 32);
        k_transpose<<<grid, dim3(32, 8)>>>(embed);
    }
    k_embed<<<NROWS, 256>>>(ids, embed, pos_enc);

    for (int i = 0; i < NLAY; i++) {
        k_rg_xm<<<NROWS, 128>>>(rg_w, rg_b, i, out + OUT_GS);
        k_ln<<<NROWS, 256>>>(pxm, n1_g + (size_t)i * DMODEL, n1_b + (size_t)i * DMODEL, pain);
        /* QKV projection */
        {
            dim3 grid((3 * DMODEL) / 128, NROWS / 128);
            k_mma_gemm<<<grid, 256, GEMM_SMEM>>>(pain, qkv_w + (size_t)i * DMODEL * 3 * DMODEL,
                                                 qkv_b + (size_t)i * 3 * DMODEL, (const float*)0,
                                                 pqkv, NROWS, 3 * DMODEL, DMODEL, 3 * DMODEL, 0);
        }
        k_ph<<<NROWS, 128>>>(ph_w, ph_b, ph_scale, i);
        {
            dim3 grid(LSEQ / 128, NHEAD, NB);
            k_attn<<<grid, 128>>>(resscale, i);
        }
        /* out projection + residual (xm) */
        {
            dim3 grid(DMODEL / 128, NROWS / 128);
            k_mma_gemm<<<grid, 256, GEMM_SMEM>>>(pao, out_w + (size_t)i * DMODEL * DMODEL,
                                                 out_b + (size_t)i * DMODEL, pxm,
                                                 px, NROWS, DMODEL, DMODEL, DMODEL, 0);
        }
        k_ln<<<NROWS, 256>>>(px, n2_g + (size_t)i * DMODEL, n2_b + (size_t)i * DMODEL, pain);
        /* FF1 + GELU */
        {
            dim3 grid(FFDIM / 128, NROWS / 128);
            k_mma_gemm<<<grid, 256, GEMM_SMEM>>>(pain, ff1_w + (size_t)i * DMODEL * FFDIM,
                                                 ff1_b + (size_t)i * FFDIM, (const float*)0,
                                                 pffh, NROWS, FFDIM, DMODEL, FFDIM, 1);
        }
        /* FF2 + residual (x) */
        {
            dim3 grid(DMODEL / 128, NROWS / 128);
            k_mma_gemm<<<grid, 256, GEMM_SMEM>>>(pffh, ff2_w + (size_t)i * FFDIM * DMODEL,
                                                 ff2_b + (size_t)i * DMODEL, px,
                                                 px, NROWS, DMODEL, FFDIM, DMODEL, 0);
        }
        /* boundary MLP layer 1 (tanh) */
        {
            dim3 grid(HIDB / 128, NROWS / 128);
            k_mma_gemm<<<grid, 256, GEMM_SMEM>>>(px, bnd_w1, bnd_b1, (const float*)0,
                                                 pbndh, NROWS, HIDB, DMODEL, HIDB, 2);
        }
        k_bnd2<<<NROWS, 128>>>(bnd_w2, bnd_b2, out + OUT_SS, i);
    }

    /* final LN -> output x region (also GEMM input) */
    k_ln<<<NROWS, 256>>>(px, fn_g, fn_b, out + OUT_X);

    /* logits = x @ embed^T via pre-transposed g_embT [D, VPAD] */
    {
        dim3 grid((VOCAB + 127) / 128, NROWS / 128);
        k_mma_gemm<<<grid, 256, GEMM_SMEM>>>(out + OUT_X, pembT, (const float*)0, (const float*)0,
                                             out + OUT_LOGITS, NROWS, VOCAB, DMODEL, VPAD, 0);
    }

    k_means<<<(NROWS * 4 + NROWS + 255) / 256, 256>>>(out);
}

// round 4
// speedup vs baseline: 2.4080x; 1.0309x over previous
#include <cuda_runtime.h>
#include <math.h>
#include <stdint.h>

#define NB      2
#define LSEQ    1024
#define DMODEL  1024
#define NHEAD   16
#define DHEAD   64
#define NLAY    6
#define VOCAB   30000
#define VPAD    30080
#define HIDB    512
#define FFDIM   4096
#define NROWS   2048   /* NB*LSEQ */

/* ---- output layout (flattened tuple, in reference return order) ---- */
static const size_t OUT_LOGITS = 0;
static const size_t OUT_X   = (size_t)NROWS * VOCAB;
static const size_t OUT_GSM = OUT_X   + (size_t)NROWS * DMODEL;
static const size_t OUT_SSM = OUT_GSM + (size_t)NROWS * 4;
static const size_t OUT_GS  = OUT_SSM + (size_t)NROWS;
static const size_t OUT_SS  = OUT_GS  + (size_t)NLAY * NROWS * 4;

/* ---- converted-weight scratch layout (floats) ---- */
#define W_QKV 0UL
#define W_OUT (W_QKV + (size_t)NLAY * DMODEL * 3 * DMODEL)
#define W_FF1 (W_OUT + (size_t)NLAY * DMODEL * DMODEL)
#define W_FF2 (W_FF1 + (size_t)NLAY * DMODEL * FFDIM)
#define W_BND (W_FF2 + (size_t)NLAY * FFDIM * DMODEL)
#define W_TOT (W_BND + (size_t)DMODEL * HIDB)

/* ---- scratch ---- */
__device__ float g_x  [NROWS * DMODEL];
__device__ float g_xm [NROWS * DMODEL];
__device__ float g_ain[NROWS * DMODEL];
__device__ float g_qkv[NROWS * 3 * DMODEL];
__device__ float g_pv [NROWS * NHEAD];
__device__ float g_ao [NROWS * DMODEL];
__device__ float g_ffh[NROWS * FFDIM];
__device__ float g_bndh[NROWS * HIDB];
__device__ float g_embT[(size_t)DMODEL * VPAD];   /* embed^T (tf32-rounded) */
__device__ float g_wc [W_TOT];                    /* tf32-rounded weights */

/* ================= low-level helpers (compute_103-safe) ================= */
__device__ __forceinline__ uint32_t smem_u32(const void* p) {
    uint32_t a;
    asm("{ .reg .u64 t; cvta.to.shared.u64 t, %1; cvt.u32.u64 %0, t; }" : "=r"(a) : "l"(p));
    return a;
}
__device__ __forceinline__ void cp16(void* s, const void* g) {
    asm volatile("cp.async.cg.shared.global [%0], [%1], 16;"
                 :: "r"(smem_u32(s)), "l"(g) : "memory");
}
#define CP_COMMIT() asm volatile("cp.async.commit_group;" ::: "memory")
#define CP_WAIT1()  asm volatile("cp.async.wait_group 1;" ::: "memory")
#define CP_WAIT0()  asm volatile("cp.async.wait_group 0;" ::: "memory")

__device__ __forceinline__ float tf32r(float f) {
    uint32_t r;
    asm("cvt.rna.tf32.f32 %0, %1;" : "=r"(r) : "f"(f));
    return __uint_as_float(r);
}
__device__ __forceinline__ void mma_m16n8k8(float* c, const uint32_t* a, const uint32_t* b) {
    asm volatile(
        "mma.sync.aligned.m16n8k8.row.col.f32.tf32.tf32.f32 "
        "{%0,%1,%2,%3}, {%4,%5,%6,%7}, {%8,%9}, {%0,%1,%2,%3};"
        : "+f"(c[0]), "+f"(c[1]), "+f"(c[2]), "+f"(c[3])
        : "r"(a[0]), "r"(a[1]), "r"(a[2]), "r"(a[3]), "r"(b[0]), "r"(b[1]));
}

/* ================= weight tf32 pre-conversion ================= */
__global__ void k_cvtw(const float4* __restrict__ src, float4* __restrict__ dst, int n4)
{
    int i = blockIdx.x * blockDim.x + threadIdx.x;
    int stride = gridDim.x * blockDim.x;
    for (; i < n4; i += stride) {
        float4 v = src[i];
        v.x = tf32r(v.x); v.y = tf32r(v.y); v.z = tf32r(v.z); v.w = tf32r(v.w);
        dst[i] = v;
    }
}

/* ================= tf32 mma GEMM (inputs pre-rounded to tf32) =================
   C[M,N] = act(A[M,K] @ B[K,N] + bias) (+resid); B row length = ldb.
   act: 0 none, 1 exact GELU, 2 tanh.  rndC: round C to tf32.
   C2: optional second output, always tf32-rounded. */
__global__ __launch_bounds__(256, 2)
void k_mma_gemm(const float* __restrict__ A, const float* __restrict__ Bm,
                const float* __restrict__ bias, const float* __restrict__ resid,
                float* __restrict__ C, float* __restrict__ C2,
                int M, int N, int K, int ldb, int act, int rndC)
{
    extern __shared__ float smem[];
    float* As = smem;              /* 2 stages x 4096 floats */
    float* Bs = smem + 2 * 4096;   /* 2 stages x 4096 floats */

    const int tid  = threadIdx.x;
    const int wid  = tid >> 5;
    const int lane = tid & 31;
    const int m0 = blockIdx.y * 128;
    const int n0 = blockIdx.x * 128;
    const int wm = (wid & 1) * 64;
    const int wn = (wid >> 1) * 32;
    const int nch = K / 32;

    const int a_row = tid >> 3, a_c4 = tid & 7;
    const int b_kr  = tid >> 5, b_c4 = tid & 31;
    const uint32_t a_dst = (uint32_t)a_row * 32u + (uint32_t)((a_c4 ^ (a_row & 7)) * 4);
    const uint32_t b_dst = (uint32_t)b_kr * 128u + (uint32_t)((b_c4 * 4) ^ ((b_kr & 3) * 8));
    const float* a_src0 = A + (size_t)(m0 + a_row) * K + a_c4 * 4;
    const float* b_src0 = Bm + (size_t)b_kr * ldb + n0 + b_c4 * 4;

    #define STAGE(c, s) do {                                                   \
        float* as = As + (s) * 4096;                                           \
        float* bs = Bs + (s) * 4096;                                           \
        const float* ap = a_src0 + (c) * 32;                                   \
        const float* bp = b_src0 + (size_t)(c) * 32 * ldb;                     \
        _Pragma("unroll")                                                      \
        for (int it = 0; it < 4; it++)                                         \
            cp16(as + a_dst + it * (32 * 32), ap + (size_t)(it * 32) * K);     \
        _Pragma("unroll")                                                      \
        for (int it = 0; it < 4; it++)                                         \
            cp16(bs + b_dst + it * (8 * 128), bp + (size_t)(it * 8) * ldb);    \
    } while (0)

    float cf[4][4][4];
    #pragma unroll
    for (int i = 0; i < 4; i++)
        #pragma unroll
        for (int j = 0; j < 4; j++)
            { cf[i][j][0] = 0.f; cf[i][j][1] = 0.f; cf[i][j][2] = 0.f; cf[i][j][3] = 0.f; }

    STAGE(0, 0);
    CP_COMMIT();

    const int fa_r = lane >> 2;
    const int fa_t = lane & 3;

    for (int c = 0; c < nch; c++) {
        if (c + 1 < nch) { STAGE(c + 1, (c + 1) & 1); CP_COMMIT(); CP_WAIT1(); }
        else             { CP_WAIT0(); }
        __syncthreads();

        const float* as = As + (c & 1) * 4096;
        const float* bs = Bs + (c & 1) * 4096;

        #pragma unroll
        for (int kk = 0; kk < 4; kk++) {
            const int k = kk * 8;
            uint32_t af[4][4];
            #pragma unroll
            for (int mt = 0; mt < 4; mt++) {
                int r = wm + mt * 16 + fa_r;
                int col0 = k + fa_t;
                int col1 = col0 + 4;
                uint32_t base = (uint32_t)r * 32u;
                uint32_t sw = (uint32_t)(r & 7);
                af[mt][0] = __float_as_uint(as[base + ((((uint32_t)col0 >> 2) ^ sw) * 4u) + (col0 & 3)]);
                af[mt][2] = __float_as_uint(as[base + ((((uint32_t)col1 >> 2) ^ sw) * 4u) + (col1 & 3)]);
                uint32_t base8 = base + 8u * 32u;
                af[mt][1] = __float_as_uint(as[base8 + ((((uint32_t)col0 >> 2) ^ sw) * 4u) + (col0 & 3)]);
                af[mt][3] = __float_as_uint(as[base8 + ((((uint32_t)col1 >> 2) ^ sw) * 4u) + (col1 & 3)]);
            }
            uint32_t bf[4][2];
            #pragma unroll
            for (int nt = 0; nt < 4; nt++) {
                int n = wn + nt * 8 + fa_r;
                int r0 = k + fa_t;
                int r1 = r0 + 4;
                bf[nt][0] = __float_as_uint(bs[(uint32_t)r0 * 128u + ((uint32_t)n ^ (uint32_t)((r0 & 3) * 8))]);
                bf[nt][1] = __float_as_uint(bs[(uint32_t)r1 * 128u + ((uint32_t)n ^ (uint32_t)((r1 & 3) * 8))]);
            }
            #pragma unroll
            for (int mt = 0; mt < 4; mt++)
                #pragma unroll
                for (int nt = 0; nt < 4; nt++)
                    mma_m16n8k8(cf[mt][nt], af[mt], bf[nt]);
        }
        __syncthreads();
    }
    #undef STAGE

    #pragma unroll
    for (int mt = 0; mt < 4; mt++) {
        int row = m0 + wm + mt * 16 + (lane >> 2);
        #pragma unroll
        for (int nt = 0; nt < 4; nt++) {
            int col = n0 + wn + nt * 8 + (lane & 3) * 2;
            if (col < N) {
                #pragma unroll
                for (int half = 0; half < 2; half++) {
                    int r = row + half * 8;
                    float v0 = cf[mt][nt][half * 2 + 0];
                    float v1 = cf[mt][nt][half * 2 + 1];
                    if (bias) { v0 += bias[col]; v1 += bias[col + 1]; }
                    if (act == 1) {
                        v0 = 0.5f * v0 * (1.0f + erff(v0 * 0.70710678118654752f));
                        v1 = 0.5f * v1 * (1.0f + erff(v1 * 0.70710678118654752f));
                    } else if (act == 2) {
                        v0 = tanhf(v0); v1 = tanhf(v1);
                    }
                    if (resid) {
                        v0 += resid[(size_t)r * N + col];
                        v1 += resid[(size_t)r * N + col + 1];
                    }
                    float s0 = rndC ? tf32r(v0) : v0;
                    float s1 = rndC ? tf32r(v1) : v1;
                    *(float2*)(C + (size_t)r * N + col) = make_float2(s0, s1);
                    if (C2)
                        *(float2*)(C2 + (size_t)r * N + col) = make_float2(tf32r(v0), tf32r(v1));
                }
            }
        }
    }
}

/* ================= embed transpose (+ tf32 round) ================= */
__global__ void k_transpose(const float* __restrict__ in)
{
    __shared__ float t[32][33];
    int v0 = blockIdx.x * 32, d0 = blockIdx.y * 32;
    int tx = threadIdx.x, ty = threadIdx.y;     /* 32 x 8 */
    #pragma unroll
    for (int i = 0; i < 4; i++) {
        int v = v0 + ty + i * 8;
        if (v < VOCAB) t[ty + i * 8][tx] = in[(size_t)v * DMODEL + d0 + tx];
    }
    __syncthreads();
    #pragma unroll
    for (int i = 0; i < 4; i++) {
        int v = v0 + tx;
        if (v < VOCAB)
            g_embT[(size_t)(d0 + ty + i * 8) * VPAD + v] = tf32r(t[tx][ty + i * 8]);
    }
}

/* ================= embedding + positional ================= */
__global__ void k_embed(const int* __restrict__ ids,
                        const float* __restrict__ emb,
                        const float* __restrict__ pos)
{
    int r = blockIdx.x;
    int l = r % LSEQ;
    int id = ids[r];
    const float4* e4 = (const float4*)(emb + (size_t)id * DMODEL);
    const float4* p4 = (const float4*)(pos + (size_t)l * DMODEL);
    float4* x4 = (float4*)(g_x + (size_t)r * DMODEL);
    for (int k = threadIdx.x; k < DMODEL / 4; k += blockDim.x) {
        float4 e = e4[k], p = p4[k];
        float4 o;
        o.x = e.x * 32.0f + p.x;
        o.y = e.y * 32.0f + p.y;
        o.z = e.z * 32.0f + p.z;
        o.w = e.w * 32.0f + p.w;
        x4[k] = o;
    }
}

/* ================= R-grammar gate + xm modulation ================= */
__global__ void k_rg_xm(const float* __restrict__ rg_w,
                        const float* __restrict__ rg_b,
                        int layer, float* __restrict__ gs_out)
{
    int r = blockIdx.x;
    int t = threadIdx.x;               /* 128 threads */
    const float* xr = g_x + (size_t)r * DMODEL;
    const float4* w4 = (const float4*)(rg_w + (size_t)layer * DMODEL * 4);
    float s0 = 0.f, s1 = 0.f, s2 = 0.f, s3 = 0.f;
    for (int k = t; k < DMODEL; k += 128) {
        float xv = xr[k];
        float4 w = w4[k];
        s0 += xv * w.x; s1 += xv * w.y; s2 += xv * w.z; s3 += xv * w.w;
    }
    for (int o = 16; o > 0; o >>= 1) {
        s0 += __shfl_down_sync(0xffffffffu, s0, o);
        s1 += __shfl_down_sync(0xffffffffu, s1, o);
        s2 += __shfl_down_sync(0xffffffffu, s2, o);
        s3 += __shfl_down_sync(0xffffffffu, s3, o);
    }
    __shared__ float red[4][4];
    __shared__ float mscale;
    int w = t >> 5, lane = t & 31;
    if (lane == 0) { red[w][0] = s0; red[w][1] = s1; red[w][2] = s2; red[w][3] = s3; }
    __syncthreads();
    if (t == 0) {
        float sum4 = 0.f;
        float* gsp = gs_out + ((size_t)layer * NROWS + r) * 4;
        #pragma unroll
        for (int n = 0; n < 4; n++) {
            float a = red[0][n] + red[1][n] + red[2][n] + red[3][n] + rg_b[layer * 4 + n];
            float sg = 1.0f / (1.0f + expf(-a));
            gsp[n] = sg;
            sum4 += sg;
        }
        mscale = 1.0f + 0.1f * (sum4 * 0.25f);
    }
    __syncthreads();
    float ms = mscale;
    const float4* x4 = (const float4*)xr;
    float4* xm4 = (float4*)(g_xm + (size_t)r * DMODEL);
    for (int k = t; k < DMODEL / 4; k += 128) {
        float4 v = x4[k];
        v.x *= ms; v.y *= ms; v.z *= ms; v.w *= ms;
        xm4[k] = v;
    }
}

/* ================= LayerNorm =================
   rnd: round main output to tf32.  out2: optional tf32-rounded copy. */
__global__ void k_ln(const float* __restrict__ in,
                     const float* __restrict__ g,
                     const float* __restrict__ b,
                     float* __restrict__ out,
                     float* __restrict__ out2, int rnd)
{
    int r = blockIdx.x, t = threadIdx.x;  /* 256 threads, 1024 floats/row */
    const float4* i4 = (const float4*)(in + (size_t)r * DMODEL);
    float4 v = i4[t];
    float s = v.x + v.y + v.z + v.w;
    float q = v.x * v.x + v.y * v.y + v.z * v.z + v.w * v.w;
    for (int o = 16; o > 0; o >>= 1) {
        s += __shfl_down_sync(0xffffffffu, s, o);
        q += __shfl_down_sync(0xffffffffu, q, o);
    }
    __shared__ float sr[8], qr[8];
    __shared__ float smean, sinv;
    if ((t & 31) == 0) { sr[t >> 5] = s; qr[t >> 5] = q; }
    __syncthreads();
    if (t == 0) {
        float S = 0.f, Q = 0.f;
        #pragma unroll
        for (int i = 0; i < 8; i++) { S += sr[i]; Q += qr[i]; }
        float mean = S * (1.0f / DMODEL);
        float var = Q * (1.0f / DMODEL) - mean * mean;
        smean = mean;
        sinv = rsqrtf(var + 1e-5f);
    }
    __syncthreads();
    float mean = smean, inv = sinv;
    float4 gg = ((const float4*)g)[t];
    float4 bb = ((const float4*)b)[t];
    float4 o;
    o.x = (v.x - mean) * inv * gg.x + bb.x;
    o.y = (v.y - mean) * inv * gg.y + bb.y;
    o.z = (v.z - mean) * inv * gg.z + bb.z;
    o.w = (v.w - mean) * inv * gg.w + bb.w;
    float4 om = o;
    if (rnd) { om.x = tf32r(o.x); om.y = tf32r(o.y); om.z = tf32r(o.z); om.w = tf32r(o.w); }
    ((float4*)(out + (size_t)r * DMODEL))[t] = om;
    if (out2) {
        float4 o2;
        o2.x = tf32r(o.x); o2.y = tf32r(o.y); o2.z = tf32r(o.z); o2.w = tf32r(o.w);
        ((float4*)(out2 + (size_t)r * DMODEL))[t] = o2;
    }
}

/* ================= phase vector ================= */
__global__ void k_ph(const float* __restrict__ ph_w,
                     const float* __restrict__ ph_b,
                     const float* __restrict__ ph_scale, int layer)
{
    int r = blockIdx.x, t = threadIdx.x;   /* 128 threads */
    const float* ar = g_ain + (size_t)r * DMODEL;
    const float4* w4 = (const float4*)(ph_w + (size_t)layer * DMODEL * NHEAD);
    float acc[16];
    #pragma unroll
    for (int n = 0; n < 16; n++) acc[n] = 0.f;
    for (int k = t; k < DMODEL; k += 128) {
        float a = ar[k];
        #pragma unroll
        for (int q = 0; q < 4; q++) {
            float4 w = w4[k * 4 + q];
            acc[q * 4 + 0] += a * w.x;
            acc[q * 4 + 1] += a * w.y;
            acc[q * 4 + 2] += a * w.z;
            acc[q * 4 + 3] += a * w.w;
        }
    }
    __shared__ float red[128][16];
    #pragma unroll
    for (int n = 0; n < 16; n++) red[t][n] = acc[n];
    __syncthreads();
    for (int s = 64; s >= 1; s >>= 1) {
        if (t < s) {
            #pragma unroll
            for (int n = 0; n < 16; n++) red[t][n] += red[t + s][n];
        }
        __syncthreads();
    }
    if (t < 16) {
        float v = red[0][t] + ph_b[layer * NHEAD + t];
        g_pv[(size_t)r * NHEAD + t] = tanhf(ph_scale[layer] * v);
    }
}

/* ================= fused attention ================= */
__global__ __launch_bounds__(128)
void k_attn(const float* __restrict__ res_scale, int layer)
{
    int b = blockIdx.z, h = blockIdx.y, rb = blockIdx.x;
    int t = threadIdx.x;
    int l = rb * 128 + t;
    float rs = res_scale[layer];

    __shared__ float4 Ks4[32 * 16];
    __shared__ float4 Vs4[32 * 16];
    __shared__ float  pvs[32];

    const float* qptr = g_qkv + ((size_t)(b * LSEQ + l) * 3 * DMODEL) + h * DHEAD;
    float4 q4[16];
    #pragma unroll
    for (int i = 0; i < 16; i++) q4[i] = ((const float4*)qptr)[i];
    float pvq = g_pv[(size_t)(b * LSEQ + l) * NHEAD + h];

    float4 o4[16];
    #pragma unroll
    for (int i = 0; i < 16; i++) o4[i] = make_float4(0.f, 0.f, 0.f, 0.f);
    float mrun = -1e30f, denom = 0.f;

    for (int m0 = 0; m0 < LSEQ; m0 += 32) {
        for (int i = t; i < 512; i += 128) {
            int row = i >> 4, f = i & 15;
            const float* kp = g_qkv + ((size_t)(b * LSEQ + m0 + row) * 3 * DMODEL) + DMODEL + h * DHEAD;
            Ks4[row * 16 + f] = ((const float4*)kp)[f];
            Vs4[row * 16 + f] = ((const float4*)(kp + DMODEL))[f];
        }
        if (t < 32) pvs[t] = g_pv[(size_t)(b * LSEQ + m0 + t) * NHEAD + h];
        __syncthreads();

        float s[32];
        float tmax = -1e30f;
        #pragma unroll
        for (int j = 0; j < 32; j++) {
            float sj = 0.f;
            #pragma unroll
            for (int i = 0; i < 16; i++) {
                float4 kv = Ks4[j * 16 + i];
                sj += q4[i].x * kv.x + q4[i].y * kv.y + q4[i].z * kv.z + q4[i].w * kv.w;
            }
            float dp = pvq - pvs[j];
            sj = sj * 0.125f - rs * dp * dp;
            s[j] = sj;
            tmax = fmaxf(tmax, sj);
        }
        float mnew = fmaxf(mrun, tmax);
        float corr = expf(mrun - mnew);
        denom *= corr;
        #pragma unroll
        for (int i = 0; i < 16; i++) {
            o4[i].x *= corr; o4[i].y *= corr; o4[i].z *= corr; o4[i].w *= corr;
        }
        #pragma unroll
        for (int j = 0; j < 32; j++) {
            float p = expf(s[j] - mnew);
            denom += p;
            #pragma unroll
            for (int i = 0; i < 16; i++) {
                float4 vv = Vs4[j * 16 + i];
                o4[i].x += p * vv.x; o4[i].y += p * vv.y;
                o4[i].z += p * vv.z; o4[i].w += p * vv.w;
            }
        }
        mrun = mnew;
        __syncthreads();
    }
    float inv = 1.0f / denom;
    float4* op = (float4*)(g_ao + (size_t)(b * LSEQ + l) * DMODEL + h * DHEAD);
    #pragma unroll
    for (int i = 0; i < 16; i++) {
        float4 o = o4[i];
        o.x = tf32r(o.x * inv); o.y = tf32r(o.y * inv);
        o.z = tf32r(o.z * inv); o.w = tf32r(o.w * inv);
        op[i] = o;
    }
}

/* ================= boundary scalar ================= */
__global__ void k_bnd2(const float* __restrict__ w2,
                       const float* __restrict__ b2,
                       float* __restrict__ ss_out, int layer)
{
    int r = blockIdx.x, t = threadIdx.x;   /* 128 threads */
    const float* hr = g_bndh + (size_t)r * HIDB;
    float s = 0.f;
    for (int k = t; k < HIDB; k += 128) s += hr[k] * w2[k];
    for (int o = 16; o > 0; o >>= 1) s += __shfl_down_sync(0xffffffffu, s, o);
    __shared__ float red[4];
    if ((t & 31) == 0) red[t >> 5] = s;
    __syncthreads();
    if (t == 0) {
        float v = red[0] + red[1] + red[2] + red[3] + b2[0];
        ss_out[(size_t)layer * NROWS + r] = 1.0f / (1.0f + expf(-v));
    }
}

/* ================= means over layers ================= */
__global__ void k_means(float* out)
{
    int idx = blockIdx.x * 256 + threadIdx.x;
    if (idx < NROWS * 4) {
        float s = 0.f;
        #pragma unroll
        for (int l = 0; l < NLAY; l++) s += out[OUT_GS + (size_t)l * NROWS * 4 + idx];
        out[OUT_GSM + idx] = s * (1.0f / NLAY);
    }
    int idx2 = idx - NROWS * 4;
    if (idx2 >= 0 && idx2 < NROWS) {
        float s = 0.f;
        #pragma unroll
        for (int l = 0; l < NLAY; l++) s += out[OUT_SS + (size_t)l * NROWS + idx2];
        out[OUT_SSM + idx2] = s * (1.0f / NLAY);
    }
}

/* ================= host ================= */
#define GEMM_SMEM (4 * 4096 * 4)   /* 64 KB */

extern "C" void kernel_launch(void* const* d_in, const int* in_sizes, int n_in,
                              void* d_out, int out_size)
{
    const int*   ids      = (const int*)  d_in[0];
    const float* embed    = (const float*)d_in[1];
    const float* pos_enc  = (const float*)d_in[2];
    const float* rg_w     = (const float*)d_in[3];
    const float* rg_b     = (const float*)d_in[4];
    const float* qkv_w    = (const float*)d_in[5];
    const float* qkv_b    = (const float*)d_in[6];
    const float* out_w    = (const float*)d_in[7];
    const float* out_b    = (const float*)d_in[8];
    const float* ph_w     = (const float*)d_in[9];
    const float* ph_b     = (const float*)d_in[10];
    const float* resscale = (const float*)d_in[11];
    const float* ph_scale = (const float*)d_in[12];
    const float* ff1_w    = (const float*)d_in[13];
    const float* ff1_b    = (const float*)d_in[14];
    const float* ff2_w    = (const float*)d_in[15];
    const float* ff2_b    = (const float*)d_in[16];
    const float* n1_g     = (const float*)d_in[17];
    const float* n1_b     = (const float*)d_in[18];
    const float* n2_g     = (const float*)d_in[19];
    const float* n2_b     = (const float*)d_in[20];
    const float* bnd_w1   = (const float*)d_in[21];
    const float* bnd_b1   = (const float*)d_in[22];
    const float* bnd_w2   = (const float*)d_in[23];
    const float* bnd_b2   = (const float*)d_in[24];
    const float* fn_g     = (const float*)d_in[25];
    const float* fn_b     = (const float*)d_in[26];
    float* out = (float*)d_out;

    float *px, *pxm, *pain, *pqkv, *pao, *pffh, *pbndh, *pembT, *pwc;
    cudaGetSymbolAddress((void**)&px,    g_x);
    cudaGetSymbolAddress((void**)&pxm,   g_xm);
    cudaGetSymbolAddress((void**)&pain,  g_ain);
    cudaGetSymbolAddress((void**)&pqkv,  g_qkv);
    cudaGetSymbolAddress((void**)&pao,   g_ao);
    cudaGetSymbolAddress((void**)&pffh,  g_ffh);
    cudaGetSymbolAddress((void**)&pbndh, g_bndh);
    cudaGetSymbolAddress((void**)&pembT, g_embT);
    cudaGetSymbolAddress((void**)&pwc,   g_wc);

    cudaFuncSetAttribute(k_mma_gemm, cudaFuncAttributeMaxDynamicSharedMemorySize, GEMM_SMEM);

    /* weight pre-conversion to tf32 */
    k_cvtw<<<2048, 256>>>((const float4*)qkv_w, (float4*)(pwc + W_QKV), (int)(W_OUT - W_QKV) / 4);
    k_cvtw<<<1024, 256>>>((const float4*)out_w, (float4*)(pwc + W_OUT), (int)(W_FF1 - W_OUT) / 4);
    k_cvtw<<<2048, 256>>>((const float4*)ff1_w, (float4*)(pwc + W_FF1), (int)(W_FF2 - W_FF1) / 4);
    k_cvtw<<<2048, 256>>>((const float4*)ff2_w, (float4*)(pwc + W_FF2), (int)(W_BND - W_FF2) / 4);
    k_cvtw<<<256, 256>>>((const float4*)bnd_w1, (float4*)(pwc + W_BND), (int)(W_TOT - W_BND) / 4);
    {
        dim3 grid((VOCAB + 31) / 32, DMODEL / 32);
        k_transpose<<<grid, dim3(32, 8)>>>(embed);
    }
    k_embed<<<NROWS, 256>>>(ids, embed, pos_enc);

    for (int i = 0; i < NLAY; i++) {
        k_rg_xm<<<NROWS, 128>>>(rg_w, rg_b, i, out + OUT_GS);
        /* pre-norm 1: rounded output (feeds QKV A + k_ph) */
        k_ln<<<NROWS, 256>>>(pxm, n1_g + (size_t)i * DMODEL, n1_b + (size_t)i * DMODEL,
                             pain, (float*)0, 1);
        /* QKV projection */
        {
            dim3 grid((3 * DMODEL) / 128, NROWS / 128);
            k_mma_gemm<<<grid, 256, GEMM_SMEM>>>(pain, pwc + W_QKV + (size_t)i * DMODEL * 3 * DMODEL,
                                                 qkv_b + (size_t)i * 3 * DMODEL, (const float*)0,
                                                 pqkv, (float*)0, NROWS, 3 * DMODEL, DMODEL, 3 * DMODEL, 0, 0);
        }
        k_ph<<<NROWS, 128>>>(ph_w, ph_b, ph_scale, i);
        {
            dim3 grid(LSEQ / 128, NHEAD, NB);
            k_attn<<<grid, 128>>>(resscale, i);
        }
        /* out projection + residual (xm) -> px (fp32) */
        {
            dim3 grid(DMODEL / 128, NROWS / 128);
            k_mma_gemm<<<grid, 256, GEMM_SMEM>>>(pao, pwc + W_OUT + (size_t)i * DMODEL * DMODEL,
                                                 out_b + (size_t)i * DMODEL, pxm,
                                                 px, (float*)0, NROWS, DMODEL, DMODEL, DMODEL, 0, 0);
        }
        /* pre-norm 2: rounded output (feeds FF1 A) */
        k_ln<<<NROWS, 256>>>(px, n2_g + (size_t)i * DMODEL, n2_b + (size_t)i * DMODEL,
                             pain, (float*)0, 1);
        /* FF1 + GELU, rounded output (feeds FF2 A) */
        {
            dim3 grid(FFDIM / 128, NROWS / 128);
            k_mma_gemm<<<grid, 256, GEMM_SMEM>>>(pain, pwc + W_FF1 + (size_t)i * DMODEL * FFDIM,
                                                 ff1_b + (size_t)i * FFDIM, (const float*)0,
                                                 pffh, (float*)0, NROWS, FFDIM, DMODEL, FFDIM, 1, 1);
        }
        /* FF2 + residual -> px (fp32) AND rounded copy -> pain (boundary A) */
        {
            dim3 grid(DMODEL / 128, NROWS / 128);
            k_mma_gemm<<<grid, 256, GEMM_SMEM>>>(pffh, pwc + W_FF2 + (size_t)i * FFDIM * DMODEL,
                                                 ff2_b + (size_t)i * DMODEL, px,
                                                 px, pain, NROWS, DMODEL, FFDIM, DMODEL, 0, 0);
        }
        /* boundary MLP layer 1 (tanh) on rounded copy */
        {
            dim3 grid(HIDB / 128, NROWS / 128);
            k_mma_gemm<<<grid, 256, GEMM_SMEM>>>(pain, pwc + W_BND, bnd_b1, (const float*)0,
                                                 pbndh, (float*)0, NROWS, HIDB, DMODEL, HIDB, 2, 0);
        }
        k_bnd2<<<NROWS, 128>>>(bnd_w2, bnd_b2, out + OUT_SS, i);
    }

    /* final LN -> fp32 x output + rounded copy for logits A */
    k_ln<<<NROWS, 256>>>(px, fn_g, fn_b, out + OUT_X, pain, 0);

    /* logits = x @ embed^T via pre-transposed, pre-rounded g_embT */
    {
        dim3 grid((VOCAB + 127) / 128, NROWS / 128);
        k_mma_gemm<<<grid, 256, GEMM_SMEM>>>(pain, pembT, (const float*)0, (const float*)0,
                                             out + OUT_LOGITS, (float*)0, NROWS, VOCAB, DMODEL, VPAD, 0, 0);
    }

    k_means<<<(NROWS * 4 + NROWS + 255) / 256, 256>>>(out);
}

// round 5
// speedup vs baseline: 3.2482x; 1.3489x over previous
#include <cuda_runtime.h>
#include <cuda_fp16.h>
#include <math.h>
#include <stdint.h>

#define NB      2
#define LSEQ    1024
#define DMODEL  1024
#define NHEAD   16
#define DHEAD   64
#define NLAY    6
#define VOCAB   30000
#define VPAD    30080
#define HIDB    512
#define FFDIM   4096
#define NROWS   2048   /* NB*LSEQ */

/* ---- output layout (flattened tuple, in reference return order) ---- */
static const size_t OUT_LOGITS = 0;
static const size_t OUT_X   = (size_t)NROWS * VOCAB;
static const size_t OUT_GSM = OUT_X   + (size_t)NROWS * DMODEL;
static const size_t OUT_SSM = OUT_GSM + (size_t)NROWS * 4;
static const size_t OUT_GS  = OUT_SSM + (size_t)NROWS;
static const size_t OUT_SS  = OUT_GS  + (size_t)NLAY * NROWS * 4;

/* ---- transposed fp16 weight scratch layout (elements) ---- */
#define W_QKV 0UL
#define W_OUT (W_QKV + (size_t)NLAY * DMODEL * 3 * DMODEL)
#define W_FF1 (W_OUT + (size_t)NLAY * DMODEL * DMODEL)
#define W_FF2 (W_FF1 + (size_t)NLAY * DMODEL * FFDIM)
#define W_BND (W_FF2 + (size_t)NLAY * FFDIM * DMODEL)
#define W_TOT (W_BND + (size_t)DMODEL * HIDB)

/* ---- scratch ---- */
__device__ float g_x  [NROWS * DMODEL];
__device__ float g_xm [NROWS * DMODEL];
__device__ float g_qkv[NROWS * 3 * DMODEL];
__device__ float g_pv [NROWS * NHEAD];
__device__ float g_bndh[NROWS * HIDB];
__device__ __align__(16) __half g_ainH[NROWS * DMODEL];
__device__ __align__(16) __half g_aoH [NROWS * DMODEL];
__device__ __align__(16) __half g_ffhH[NROWS * FFDIM];
__device__ __align__(16) __half g_wh  [W_TOT];
__device__ __align__(16) __half g_embH[(size_t)VPAD * DMODEL];

/* ================= low-level helpers (compute_103-safe) ================= */
__device__ __forceinline__ uint32_t smem_u32(const void* p) {
    uint32_t a;
    asm("{ .reg .u64 t; cvta.to.shared.u64 t, %1; cvt.u32.u64 %0, t; }" : "=r"(a) : "l"(p));
    return a;
}
__device__ __forceinline__ void cp16(void* s, const void* g) {
    asm volatile("cp.async.cg.shared.global [%0], [%1], 16;"
                 :: "r"(smem_u32(s)), "l"(g) : "memory");
}
#define CP_COMMIT() asm volatile("cp.async.commit_group;" ::: "memory")
#define CP_WAIT1()  asm volatile("cp.async.wait_group 1;" ::: "memory")
#define CP_WAIT0()  asm volatile("cp.async.wait_group 0;" ::: "memory")

#define LDSM4(r0, r1, r2, r3, addr) \
    asm volatile("ldmatrix.sync.aligned.m8n8.x4.shared.b16 {%0,%1,%2,%3}, [%4];" \
                 : "=r"(r0), "=r"(r1), "=r"(r2), "=r"(r3) : "r"(addr))

__device__ __forceinline__ void mma_h(float* c, const uint32_t* a, const uint32_t* b) {
    asm volatile(
        "mma.sync.aligned.m16n8k16.row.col.f32.f16.f16.f32 "
        "{%0,%1,%2,%3}, {%4,%5,%6,%7}, {%8,%9}, {%0,%1,%2,%3};"
        : "+f"(c[0]), "+f"(c[1]), "+f"(c[2]), "+f"(c[3])
        : "r"(a[0]), "r"(a[1]), "r"(a[2]), "r"(a[3]), "r"(b[0]), "r"(b[1]));
}

/* ================= fp16 mma GEMM =================
   C[M,N](f32) / C2[M,N](fp16) = act(A[M,K] @ Bt[N,K]^T + bias) (+resid)
   A, Bt fp16 k-major.  act: 0 none, 1 exact GELU, 2 tanh. */
__global__ __launch_bounds__(256, 2)
void k_hgemm(const __half* __restrict__ A, const __half* __restrict__ Bm,
             const float* __restrict__ bias, const float* __restrict__ resid,
             float* __restrict__ C, __half* __restrict__ C2,
             int M, int N, int K, int act)
{
    extern __shared__ __half hs[];
    __half* As = hs;              /* 2 stages x 8192 halves (16 KB each) */
    __half* Bs = hs + 16384;

    const int tid  = threadIdx.x;
    const int wid  = tid >> 5;
    const int lane = tid & 31;
    const int m0 = blockIdx.y * 128;
    const int n0 = blockIdx.x * 128;
    const int wm = (wid & 1) * 64;
    const int wn = (wid >> 1) * 32;
    const int nch = K >> 6;

    /* staging: linear 16B chunk i = tid + it*256; row = i>>3 (0..127), c = i&7.
       row&7 invariant across it -> constant swizzle per thread. */
    const int st_row = tid >> 3;
    const uint32_t st_sw = (uint32_t)(((tid & 7) ^ (st_row & 7)) * 8);
    const __half* aglob = A + (size_t)(m0 + st_row) * K + (tid & 7) * 8;
    const __half* bglob = Bm + (size_t)(n0 + st_row) * K + (tid & 7) * 8;

#define HSTAGE(ch, s) do {                                                      \
    __half* as_ = As + (s) * 8192;                                              \
    __half* bs_ = Bs + (s) * 8192;                                              \
    const __half* ap = aglob + (ch) * 64;                                       \
    const __half* bp = bglob + (ch) * 64;                                       \
    _Pragma("unroll")                                                           \
    for (int it = 0; it < 4; it++) {                                            \
        cp16(as_ + (st_row + it * 32) * 64 + st_sw, ap + (size_t)(it * 32) * K);\
        cp16(bs_ + (st_row + it * 32) * 64 + st_sw, bp + (size_t)(it * 32) * K);\
    }                                                                           \
} while (0)

    /* fragment address constants */
    const int lsw = lane & 7;
    const int rA  = (lane & 7) + (lane & 8);          /* A ldmatrix row offset */
    const int rB  = (lane & 7) + ((lane & 16) >> 1);  /* B ldmatrix row offset */
    const int cA  = (lane >> 4) & 1;
    const int cB  = (lane >> 3) & 1;

    float cf[4][4][4];
    #pragma unroll
    for (int i = 0; i < 4; i++)
        #pragma unroll
        for (int j = 0; j < 4; j++)
            { cf[i][j][0] = 0.f; cf[i][j][1] = 0.f; cf[i][j][2] = 0.f; cf[i][j][3] = 0.f; }

    HSTAGE(0, 0);
    CP_COMMIT();

    for (int c = 0; c < nch; c++) {
        if (c + 1 < nch) { HSTAGE(c + 1, (c + 1) & 1); CP_COMMIT(); CP_WAIT1(); }
        else             { CP_WAIT0(); }
        __syncthreads();

        const uint32_t ab = smem_u32(As + (c & 1) * 8192);
        const uint32_t bb = smem_u32(Bs + (c & 1) * 8192);

        #pragma unroll
        for (int kk = 0; kk < 4; kk++) {
            const uint32_t sA = (uint32_t)(((kk * 2 + cA) ^ lsw) * 16);
            const uint32_t sB = (uint32_t)(((kk * 2 + cB) ^ lsw) * 16);
            uint32_t af[4][4], bf[2][4];
            #pragma unroll
            for (int mt = 0; mt < 4; mt++)
                LDSM4(af[mt][0], af[mt][1], af[mt][2], af[mt][3],
                      ab + (uint32_t)(wm + mt * 16 + rA) * 128u + sA);
            #pragma unroll
            for (int p = 0; p < 2; p++)
                LDSM4(bf[p][0], bf[p][1], bf[p][2], bf[p][3],
                      bb + (uint32_t)(wn + p * 16 + rB) * 128u + sB);
            #pragma unroll
            for (int mt = 0; mt < 4; mt++)
                #pragma unroll
                for (int nt = 0; nt < 4; nt++)
                    mma_h(cf[mt][nt], af[mt], &bf[nt >> 1][(nt & 1) * 2]);
        }
        __syncthreads();
    }
#undef HSTAGE

    /* epilogue */
    #pragma unroll
    for (int mt = 0; mt < 4; mt++) {
        int row = m0 + wm + mt * 16 + (lane >> 2);
        #pragma unroll
        for (int nt = 0; nt < 4; nt++) {
            int col = n0 + wn + nt * 8 + (lane & 3) * 2;
            if (col < N) {
                #pragma unroll
                for (int hh = 0; hh < 2; hh++) {
                    int r = row + hh * 8;
                    float v0 = cf[mt][nt][hh * 2 + 0];
                    float v1 = cf[mt][nt][hh * 2 + 1];
                    if (bias) { v0 += bias[col]; v1 += bias[col + 1]; }
                    if (act == 1) {
                        v0 = 0.5f * v0 * (1.0f + erff(v0 * 0.70710678118654752f));
                        v1 = 0.5f * v1 * (1.0f + erff(v1 * 0.70710678118654752f));
                    } else if (act == 2) {
                        v0 = tanhf(v0); v1 = tanhf(v1);
                    }
                    if (resid) {
                        v0 += resid[(size_t)r * N + col];
                        v1 += resid[(size_t)r * N + col + 1];
                    }
                    if (C)  *(float2*)(C + (size_t)r * N + col) = make_float2(v0, v1);
                    if (C2) *(__half2*)(C2 + (size_t)r * N + col) = __floats2half2_rn(v0, v1);
                }
            }
        }
    }
}

/* ================= weight transpose + fp16 convert: dst[n][k] = src[k][n] ========= */
__global__ void k_cvtT(const float* __restrict__ src, __half* __restrict__ dst,
                       int K, int N)
{
    __shared__ float t[32][33];
    int n0 = blockIdx.x * 32, k0 = blockIdx.y * 32;
    int tx = threadIdx.x, ty = threadIdx.y;   /* 32 x 8 */
    #pragma unroll
    for (int i = 0; i < 4; i++)
        t[ty + i * 8][tx] = src[(size_t)(k0 + ty + i * 8) * N + n0 + tx];
    __syncthreads();
    #pragma unroll
    for (int i = 0; i < 4; i++)
        dst[(size_t)(n0 + ty + i * 8) * K + k0 + tx] = __float2half_rn(t[tx][ty + i * 8]);
}

/* ================= embed -> fp16 [VPAD][D] with zero pad ================= */
__global__ void k_cvtE(const float* __restrict__ src)
{
    size_t stride = (size_t)gridDim.x * blockDim.x;
    size_t tot8 = (size_t)VPAD * DMODEL / 8;
    for (size_t i = (size_t)blockIdx.x * blockDim.x + threadIdx.x; i < tot8; i += stride) {
        size_t e = i * 8;
        size_t row = e / DMODEL;
        __half2 h[4];
        if (row < VOCAB) {
            float4 v0 = *(const float4*)(src + e);
            float4 v1 = *(const float4*)(src + e + 4);
            h[0] = __floats2half2_rn(v0.x, v0.y);
            h[1] = __floats2half2_rn(v0.z, v0.w);
            h[2] = __floats2half2_rn(v1.x, v1.y);
            h[3] = __floats2half2_rn(v1.z, v1.w);
        } else {
            h[0] = h[1] = h[2] = h[3] = __float2half2_rn(0.f);
        }
        *(uint4*)(g_embH + e) = *(uint4*)h;
    }
}

/* ================= embedding + positional ================= */
__global__ void k_embed(const int* __restrict__ ids,
                        const float* __restrict__ emb,
                        const float* __restrict__ pos)
{
    int r = blockIdx.x;
    int l = r % LSEQ;
    int id = ids[r];
    const float4* e4 = (const float4*)(emb + (size_t)id * DMODEL);
    const float4* p4 = (const float4*)(pos + (size_t)l * DMODEL);
    float4* x4 = (float4*)(g_x + (size_t)r * DMODEL);
    for (int k = threadIdx.x; k < DMODEL / 4; k += blockDim.x) {
        float4 e = e4[k], p = p4[k];
        float4 o;
        o.x = e.x * 32.0f + p.x;
        o.y = e.y * 32.0f + p.y;
        o.z = e.z * 32.0f + p.z;
        o.w = e.w * 32.0f + p.w;
        x4[k] = o;
    }
}

/* ================= R-grammar gate + xm modulation ================= */
__global__ void k_rg_xm(const float* __restrict__ rg_w,
                        const float* __restrict__ rg_b,
                        int layer, float* __restrict__ gs_out)
{
    int r = blockIdx.x;
    int t = threadIdx.x;               /* 128 threads */
    const float* xr = g_x + (size_t)r * DMODEL;
    const float4* w4 = (const float4*)(rg_w + (size_t)layer * DMODEL * 4);
    float s0 = 0.f, s1 = 0.f, s2 = 0.f, s3 = 0.f;
    for (int k = t; k < DMODEL; k += 128) {
        float xv = xr[k];
        float4 w = w4[k];
        s0 += xv * w.x; s1 += xv * w.y; s2 += xv * w.z; s3 += xv * w.w;
    }
    for (int o = 16; o > 0; o >>= 1) {
        s0 += __shfl_down_sync(0xffffffffu, s0, o);
        s1 += __shfl_down_sync(0xffffffffu, s1, o);
        s2 += __shfl_down_sync(0xffffffffu, s2, o);
        s3 += __shfl_down_sync(0xffffffffu, s3, o);
    }
    __shared__ float red[4][4];
    __shared__ float mscale;
    int w = t >> 5, lane = t & 31;
    if (lane == 0) { red[w][0] = s0; red[w][1] = s1; red[w][2] = s2; red[w][3] = s3; }
    __syncthreads();
    if (t == 0) {
        float sum4 = 0.f;
        float* gsp = gs_out + ((size_t)layer * NROWS + r) * 4;
        #pragma unroll
        for (int n = 0; n < 4; n++) {
            float a = red[0][n] + red[1][n] + red[2][n] + red[3][n] + rg_b[layer * 4 + n];
            float sg = 1.0f / (1.0f + expf(-a));
            gsp[n] = sg;
            sum4 += sg;
        }
        mscale = 1.0f + 0.1f * (sum4 * 0.25f);
    }
    __syncthreads();
    float ms = mscale;
    const float4* x4 = (const float4*)xr;
    float4* xm4 = (float4*)(g_xm + (size_t)r * DMODEL);
    for (int k = t; k < DMODEL / 4; k += 128) {
        float4 v = x4[k];
        v.x *= ms; v.y *= ms; v.z *= ms; v.w *= ms;
        xm4[k] = v;
    }
}

/* ================= LayerNorm: fp16 main output + optional fp32 copy ======= */
__global__ void k_ln(const float* __restrict__ in,
                     const float* __restrict__ g,
                     const float* __restrict__ b,
                     __half* __restrict__ outh,
                     float* __restrict__ outf)
{
    int r = blockIdx.x, t = threadIdx.x;  /* 256 threads, 1024 floats/row */
    const float4* i4 = (const float4*)(in + (size_t)r * DMODEL);
    float4 v = i4[t];
    float s = v.x + v.y + v.z + v.w;
    float q = v.x * v.x + v.y * v.y + v.z * v.z + v.w * v.w;
    for (int o = 16; o > 0; o >>= 1) {
        s += __shfl_down_sync(0xffffffffu, s, o);
        q += __shfl_down_sync(0xffffffffu, q, o);
    }
    __shared__ float sr[8], qr[8];
    __shared__ float smean, sinv;
    if ((t & 31) == 0) { sr[t >> 5] = s; qr[t >> 5] = q; }
    __syncthreads();
    if (t == 0) {
        float S = 0.f, Q = 0.f;
        #pragma unroll
        for (int i = 0; i < 8; i++) { S += sr[i]; Q += qr[i]; }
        float mean = S * (1.0f / DMODEL);
        float var = Q * (1.0f / DMODEL) - mean * mean;
        smean = mean;
        sinv = rsqrtf(var + 1e-5f);
    }
    __syncthreads();
    float mean = smean, inv = sinv;
    float4 gg = ((const float4*)g)[t];
    float4 bb = ((const float4*)b)[t];
    float4 o;
    o.x = (v.x - mean) * inv * gg.x + bb.x;
    o.y = (v.y - mean) * inv * gg.y + bb.y;
    o.z = (v.z - mean) * inv * gg.z + bb.z;
    o.w = (v.w - mean) * inv * gg.w + bb.w;
    __half2* hp = (__half2*)(outh + (size_t)r * DMODEL + t * 4);
    hp[0] = __floats2half2_rn(o.x, o.y);
    hp[1] = __floats2half2_rn(o.z, o.w);
    if (outf)
        ((float4*)(outf + (size_t)r * DMODEL))[t] = o;
}

/* ================= phase vector (fp16 a_in) ================= */
__global__ void k_ph(const float* __restrict__ ph_w,
                     const float* __restrict__ ph_b,
                     const float* __restrict__ ph_scale, int layer)
{
    int r = blockIdx.x, t = threadIdx.x;   /* 128 threads */
    const __half* ar = g_ainH + (size_t)r * DMODEL;
    const float4* w4 = (const float4*)(ph_w + (size_t)layer * DMODEL * NHEAD);
    float acc[16];
    #pragma unroll
    for (int n = 0; n < 16; n++) acc[n] = 0.f;
    for (int k = t; k < DMODEL; k += 128) {
        float a = __half2float(ar[k]);
        #pragma unroll
        for (int q = 0; q < 4; q++) {
            float4 w = w4[k * 4 + q];
            acc[q * 4 + 0] += a * w.x;
            acc[q * 4 + 1] += a * w.y;
            acc[q * 4 + 2] += a * w.z;
            acc[q * 4 + 3] += a * w.w;
        }
    }
    __shared__ float red[128][16];
    #pragma unroll
    for (int n = 0; n < 16; n++) red[t][n] = acc[n];
    __syncthreads();
    for (int s = 64; s >= 1; s >>= 1) {
        if (t < s) {
            #pragma unroll
            for (int n = 0; n < 16; n++) red[t][n] += red[t + s][n];
        }
        __syncthreads();
    }
    if (t < 16) {
        float v = red[0][t] + ph_b[layer * NHEAD + t];
        g_pv[(size_t)r * NHEAD + t] = tanhf(ph_scale[layer] * v);
    }
}

/* ================= fused attention (fp32 in, fp16 out) ================= */
__global__ __launch_bounds__(128)
void k_attn(const float* __restrict__ res_scale, int layer)
{
    int b = blockIdx.z, h = blockIdx.y, rb = blockIdx.x;
    int t = threadIdx.x;
    int l = rb * 128 + t;
    float rs = res_scale[layer];

    __shared__ float4 Ks4[32 * 16];
    __shared__ float4 Vs4[32 * 16];
    __shared__ float  pvs[32];

    const float* qptr = g_qkv + ((size_t)(b * LSEQ + l) * 3 * DMODEL) + h * DHEAD;
    float4 q4[16];
    #pragma unroll
    for (int i = 0; i < 16; i++) q4[i] = ((const float4*)qptr)[i];
    float pvq = g_pv[(size_t)(b * LSEQ + l) * NHEAD + h];

    float4 o4[16];
    #pragma unroll
    for (int i = 0; i < 16; i++) o4[i] = make_float4(0.f, 0.f, 0.f, 0.f);
    float mrun = -1e30f, denom = 0.f;

    for (int m0 = 0; m0 < LSEQ; m0 += 32) {
        for (int i = t; i < 512; i += 128) {
            int row = i >> 4, f = i & 15;
            const float* kp = g_qkv + ((size_t)(b * LSEQ + m0 + row) * 3 * DMODEL) + DMODEL + h * DHEAD;
            Ks4[row * 16 + f] = ((const float4*)kp)[f];
            Vs4[row * 16 + f] = ((const float4*)(kp + DMODEL))[f];
        }
        if (t < 32) pvs[t] = g_pv[(size_t)(b * LSEQ + m0 + t) * NHEAD + h];
        __syncthreads();

        float s[32];
        float tmax = -1e30f;
        #pragma unroll
        for (int j = 0; j < 32; j++) {
            float sj = 0.f;
            #pragma unroll
            for (int i = 0; i < 16; i++) {
                float4 kv = Ks4[j * 16 + i];
                sj += q4[i].x * kv.x + q4[i].y * kv.y + q4[i].z * kv.z + q4[i].w * kv.w;
            }
            float dp = pvq - pvs[j];
            sj = sj * 0.125f - rs * dp * dp;
            s[j] = sj;
            tmax = fmaxf(tmax, sj);
        }
        float mnew = fmaxf(mrun, tmax);
        float corr = expf(mrun - mnew);
        denom *= corr;
        #pragma unroll
        for (int i = 0; i < 16; i++) {
            o4[i].x *= corr; o4[i].y *= corr; o4[i].z *= corr; o4[i].w *= corr;
        }
        #pragma unroll
        for (int j = 0; j < 32; j++) {
            float p = expf(s[j] - mnew);
            denom += p;
            #pragma unroll
            for (int i = 0; i < 16; i++) {
                float4 vv = Vs4[j * 16 + i];
                o4[i].x += p * vv.x; o4[i].y += p * vv.y;
                o4[i].z += p * vv.z; o4[i].w += p * vv.w;
            }
        }
        mrun = mnew;
        __syncthreads();
    }
    float inv = 1.0f / denom;
    __half2* op = (__half2*)(g_aoH + (size_t)(b * LSEQ + l) * DMODEL + h * DHEAD);
    #pragma unroll
    for (int i = 0; i < 16; i++) {
        op[i * 2 + 0] = __floats2half2_rn(o4[i].x * inv, o4[i].y * inv);
        op[i * 2 + 1] = __floats2half2_rn(o4[i].z * inv, o4[i].w * inv);
    }
}

/* ================= boundary scalar ================= */
__global__ void k_bnd2(const float* __restrict__ w2,
                       const float* __restrict__ b2,
                       float* __restrict__ ss_out, int layer)
{
    int r = blockIdx.x, t = threadIdx.x;   /* 128 threads */
    const float* hr = g_bndh + (size_t)r * HIDB;
    float s = 0.f;
    for (int k = t; k < HIDB; k += 128) s += hr[k] * w2[k];
    for (int o = 16; o > 0; o >>= 1) s += __shfl_down_sync(0xffffffffu, s, o);
    __shared__ float red[4];
    if ((t & 31) == 0) red[t >> 5] = s;
    __syncthreads();
    if (t == 0) {
        float v = red[0] + red[1] + red[2] + red[3] + b2[0];
        ss_out[(size_t)layer * NROWS + r] = 1.0f / (1.0f + expf(-v));
    }
}

/* ================= means over layers ================= */
__global__ void k_means(float* out)
{
    int idx = blockIdx.x * 256 + threadIdx.x;
    if (idx < NROWS * 4) {
        float s = 0.f;
        #pragma unroll
        for (int l = 0; l < NLAY; l++) s += out[OUT_GS + (size_t)l * NROWS * 4 + idx];
        out[OUT_GSM + idx] = s * (1.0f / NLAY);
    }
    int idx2 = idx - NROWS * 4;
    if (idx2 >= 0 && idx2 < NROWS) {
        float s = 0.f;
        #pragma unroll
        for (int l = 0; l < NLAY; l++) s += out[OUT_SS + (size_t)l * NROWS + idx2];
        out[OUT_SSM + idx2] = s * (1.0f / NLAY);
    }
}

/* ================= host ================= */
#define GEMM_SMEM 65536   /* 2 stages x (16KB A + 16KB B) */

extern "C" void kernel_launch(void* const* d_in, const int* in_sizes, int n_in,
                              void* d_out, int out_size)
{
    const int*   ids      = (const int*)  d_in[0];
    const float* embed    = (const float*)d_in[1];
    const float* pos_enc  = (const float*)d_in[2];
    const float* rg_w     = (const float*)d_in[3];
    const float* rg_b     = (const float*)d_in[4];
    const float* qkv_w    = (const float*)d_in[5];
    const float* qkv_b    = (const float*)d_in[6];
    const float* out_w    = (const float*)d_in[7];
    const float* out_b    = (const float*)d_in[8];
    const float* ph_w     = (const float*)d_in[9];
    const float* ph_b     = (const float*)d_in[10];
    const float* resscale = (const float*)d_in[11];
    const float* ph_scale = (const float*)d_in[12];
    const float* ff1_w    = (const float*)d_in[13];
    const float* ff1_b    = (const float*)d_in[14];
    const float* ff2_w    = (const float*)d_in[15];
    const float* ff2_b    = (const float*)d_in[16];
    const float* n1_g     = (const float*)d_in[17];
    const float* n1_b     = (const float*)d_in[18];
    const float* n2_g     = (const float*)d_in[19];
    const float* n2_b     = (const float*)d_in[20];
    const float* bnd_w1   = (const float*)d_in[21];
    const float* bnd_b1   = (const float*)d_in[22];
    const float* bnd_w2   = (const float*)d_in[23];
    const float* bnd_b2   = (const float*)d_in[24];
    const float* fn_g     = (const float*)d_in[25];
    const float* fn_b     = (const float*)d_in[26];
    float* out = (float*)d_out;

    float *px, *pxm, *pqkv, *pbndh;
    __half *painH, *paoH, *pffhH, *pwh, *pembH;
    cudaGetSymbolAddress((void**)&px,    g_x);
    cudaGetSymbolAddress((void**)&pxm,   g_xm);
    cudaGetSymbolAddress((void**)&pqkv,  g_qkv);
    cudaGetSymbolAddress((void**)&pbndh, g_bndh);
    cudaGetSymbolAddress((void**)&painH, g_ainH);
    cudaGetSymbolAddress((void**)&paoH,  g_aoH);
    cudaGetSymbolAddress((void**)&pffhH, g_ffhH);
    cudaGetSymbolAddress((void**)&pwh,   g_wh);
    cudaGetSymbolAddress((void**)&pembH, g_embH);

    cudaFuncSetAttribute(k_hgemm, cudaFuncAttributeMaxDynamicSharedMemorySize, GEMM_SMEM);

    /* weight transpose + fp16 convert */
    dim3 tb(32, 8);
    for (int i = 0; i < NLAY; i++) {
        k_cvtT<<<dim3(3 * DMODEL / 32, DMODEL / 32), tb>>>(
            qkv_w + (size_t)i * DMODEL * 3 * DMODEL,
            pwh + W_QKV + (size_t)i * 3 * DMODEL * DMODEL, DMODEL, 3 * DMODEL);
        k_cvtT<<<dim3(DMODEL / 32, DMODEL / 32), tb>>>(
            out_w + (size_t)i * DMODEL * DMODEL,
            pwh + W_OUT + (size_t)i * DMODEL * DMODEL, DMODEL, DMODEL);
        k_cvtT<<<dim3(FFDIM / 32, DMODEL / 32), tb>>>(
            ff1_w + (size_t)i * DMODEL * FFDIM,
            pwh + W_FF1 + (size_t)i * DMODEL * FFDIM, DMODEL, FFDIM);
        k_cvtT<<<dim3(DMODEL / 32, FFDIM / 32), tb>>>(
            ff2_w + (size_t)i * FFDIM * DMODEL,
            pwh + W_FF2 + (size_t)i * FFDIM * DMODEL, FFDIM, DMODEL);
    }
    k_cvtT<<<dim3(HIDB / 32, DMODEL / 32), tb>>>(bnd_w1, pwh + W_BND, DMODEL, HIDB);
    k_cvtE<<<2048, 256>>>(embed);
    k_embed<<<NROWS, 256>>>(ids, embed, pos_enc);

    for (int i = 0; i < NLAY; i++) {
        k_rg_xm<<<NROWS, 128>>>(rg_w, rg_b, i, out + OUT_GS);
        /* pre-norm 1 -> fp16 a_in */
        k_ln<<<NROWS, 256>>>(pxm, n1_g + (size_t)i * DMODEL, n1_b + (size_t)i * DMODEL,
                             painH, (float*)0);
        /* QKV projection -> fp32 qkv */
        {
            dim3 grid((3 * DMODEL) / 128, NROWS / 128);
            k_hgemm<<<grid, 256, GEMM_SMEM>>>(painH, pwh + W_QKV + (size_t)i * 3 * DMODEL * DMODEL,
                                              qkv_b + (size_t)i * 3 * DMODEL, (const float*)0,
                                              pqkv, (__half*)0, NROWS, 3 * DMODEL, DMODEL, 0);
        }
        k_ph<<<NROWS, 128>>>(ph_w, ph_b, ph_scale, i);
        {
            dim3 grid(LSEQ / 128, NHEAD, NB);
            k_attn<<<grid, 128>>>(resscale, i);
        }
        /* out projection + residual (xm) -> px fp32 */
        {
            dim3 grid(DMODEL / 128, NROWS / 128);
            k_hgemm<<<grid, 256, GEMM_SMEM>>>(paoH, pwh + W_OUT + (size_t)i * DMODEL * DMODEL,
                                              out_b + (size_t)i * DMODEL, pxm,
                                              px, (__half*)0, NROWS, DMODEL, DMODEL, 0);
        }
        /* pre-norm 2 -> fp16 a_in */
        k_ln<<<NROWS, 256>>>(px, n2_g + (size_t)i * DMODEL, n2_b + (size_t)i * DMODEL,
                             painH, (float*)0);
        /* FF1 + GELU -> fp16 hidden */
        {
            dim3 grid(FFDIM / 128, NROWS / 128);
            k_hgemm<<<grid, 256, GEMM_SMEM>>>(painH, pwh + W_FF1 + (size_t)i * DMODEL * FFDIM,
                                              ff1_b + (size_t)i * FFDIM, (const float*)0,
                                              (float*)0, pffhH, NROWS, FFDIM, DMODEL, 1);
        }
        /* FF2 + residual -> px fp32 AND fp16 copy for boundary */
        {
            dim3 grid(DMODEL / 128, NROWS / 128);
            k_hgemm<<<grid, 256, GEMM_SMEM>>>(pffhH, pwh + W_FF2 + (size_t)i * FFDIM * DMODEL,
                                              ff2_b + (size_t)i * DMODEL, px,
                                              px, painH, NROWS, DMODEL, FFDIM, 0);
        }
        /* boundary MLP layer 1 (tanh) -> fp32 hidden */
        {
            dim3 grid(HIDB / 128, NROWS / 128);
            k_hgemm<<<grid, 256, GEMM_SMEM>>>(painH, pwh + W_BND, bnd_b1, (const float*)0,
                                              pbndh, (__half*)0, NROWS, HIDB, DMODEL, 2);
        }
        k_bnd2<<<NROWS, 128>>>(bnd_w2, bnd_b2, out + OUT_SS, i);
    }

    /* final LN -> fp32 x output + fp16 copy for logits A */
    k_ln<<<NROWS, 256>>>(px, fn_g, fn_b, painH, out + OUT_X);

    /* logits = x @ embed^T; embed [V,D] is already [N,K] k-major */
    {
        dim3 grid(VPAD / 128, NROWS / 128);
        k_hgemm<<<grid, 256, GEMM_SMEM>>>(painH, pembH, (const float*)0, (const float*)0,
                                          out + OUT_LOGITS, (__half*)0, NROWS, VOCAB, DMODEL, 0);
    }

    k_means<<<(NROWS * 4 + NROWS + 255) / 256, 256>>>(out);
}

// round 8
// speedup vs baseline: 5.6710x; 1.7459x over previous
#include <cuda_runtime.h>
#include <cuda_fp16.h>
#include <math.h>
#include <stdint.h>

#define NB      2
#define LSEQ    1024
#define DMODEL  1024
#define NHEAD   16
#define DHEAD   64
#define NLAY    6
#define VOCAB   30000
#define VPAD    30080
#define HIDB    512
#define FFDIM   4096
#define NROWS   2048   /* NB*LSEQ */

/* ---- output layout (flattened tuple, in reference return order) ---- */
static const size_t OUT_LOGITS = 0;
static const size_t OUT_X   = (size_t)NROWS * VOCAB;
static const size_t OUT_GSM = OUT_X   + (size_t)NROWS * DMODEL;
static const size_t OUT_SSM = OUT_GSM + (size_t)NROWS * 4;
static const size_t OUT_GS  = OUT_SSM + (size_t)NROWS;
static const size_t OUT_SS  = OUT_GS  + (size_t)NLAY * NROWS * 4;

/* ---- transposed fp16 weight scratch layout (elements) ---- */
#define W_QKV 0UL
#define W_OUT (W_QKV + (size_t)NLAY * DMODEL * 3 * DMODEL)
#define W_FF1 (W_OUT + (size_t)NLAY * DMODEL * DMODEL)
#define W_FF2 (W_FF1 + (size_t)NLAY * DMODEL * FFDIM)
#define W_BND (W_FF2 + (size_t)NLAY * FFDIM * DMODEL)
#define W_TOT (W_BND + (size_t)DMODEL * HIDB)

/* ---- scratch ---- */
__device__ float g_x  [NROWS * DMODEL];
__device__ float g_xm [NROWS * DMODEL];
__device__ float g_pv [NROWS * NHEAD];
__device__ float g_bndh[NROWS * HIDB];
__device__ __align__(16) __half g_ainH[NROWS * DMODEL];
__device__ __align__(16) __half g_aoH [NROWS * DMODEL];
__device__ __align__(16) __half g_ffhH[NROWS * FFDIM];
__device__ __align__(16) __half g_qkvH[NROWS * 3 * DMODEL];
__device__ __align__(16) __half g_vT  [(size_t)NB * NHEAD * DHEAD * LSEQ];
__device__ __align__(16) __half g_wh  [W_TOT];
__device__ __align__(16) __half g_embH[(size_t)VPAD * DMODEL];

/* ================= low-level helpers (compute_103-safe) ================= */
__device__ __forceinline__ uint32_t smem_u32(const void* p) {
    uint32_t a;
    asm("{ .reg .u64 t; cvta.to.shared.u64 t, %1; cvt.u32.u64 %0, t; }" : "=r"(a) : "l"(p));
    return a;
}
__device__ __forceinline__ void cp16(void* s, const void* g) {
    asm volatile("cp.async.cg.shared.global [%0], [%1], 16;"
                 :: "r"(smem_u32(s)), "l"(g) : "memory");
}
#define CP_COMMIT() asm volatile("cp.async.commit_group;" ::: "memory")
#define CP_WAIT1()  asm volatile("cp.async.wait_group 1;" ::: "memory")
#define CP_WAIT0()  asm volatile("cp.async.wait_group 0;" ::: "memory")

#define LDSM4(r0, r1, r2, r3, addr) \
    asm volatile("ldmatrix.sync.aligned.m8n8.x4.shared.b16 {%0,%1,%2,%3}, [%4];" \
                 : "=r"(r0), "=r"(r1), "=r"(r2), "=r"(r3) : "r"(addr))

__device__ __forceinline__ void mma_h(float* c, const uint32_t* a, const uint32_t* b) {
    asm volatile(
        "mma.sync.aligned.m16n8k16.row.col.f32.f16.f16.f32 "
        "{%0,%1,%2,%3}, {%4,%5,%6,%7}, {%8,%9}, {%0,%1,%2,%3};"
        : "+f"(c[0]), "+f"(c[1]), "+f"(c[2]), "+f"(c[3])
        : "r"(a[0]), "r"(a[1]), "r"(a[2]), "r"(a[3]), "r"(b[0]), "r"(b[1]));
}

/* ================= fp16 mma GEMM =================
   C[M,N](f32) / C2[M,N](fp16) = act(A[M,K] @ Bt[N,K]^T + bias) (+resid) */
__global__ __launch_bounds__(256, 2)
void k_hgemm(const __half* __restrict__ A, const __half* __restrict__ Bm,
             const float* __restrict__ bias, const float* __restrict__ resid,
             float* __restrict__ C, __half* __restrict__ C2,
             int M, int N, int K, int act)
{
    extern __shared__ __half hs[];
    __half* As = hs;              /* 2 stages x 8192 halves */
    __half* Bs = hs + 16384;

    const int tid  = threadIdx.x;
    const int wid  = tid >> 5;
    const int lane = tid & 31;
    const int m0 = blockIdx.y * 128;
    const int n0 = blockIdx.x * 128;
    const int wm = (wid & 1) * 64;
    const int wn = (wid >> 1) * 32;
    const int nch = K >> 6;

    const int st_row = tid >> 3;
    const uint32_t st_sw = (uint32_t)(((tid & 7) ^ (st_row & 7)) * 8);
    const __half* aglob = A + (size_t)(m0 + st_row) * K + (tid & 7) * 8;
    const __half* bglob = Bm + (size_t)(n0 + st_row) * K + (tid & 7) * 8;

#define HSTAGE(ch, s) do {                                                      \
    __half* as_ = As + (s) * 8192;                                              \
    __half* bs_ = Bs + (s) * 8192;                                              \
    const __half* ap = aglob + (ch) * 64;                                       \
    const __half* bp = bglob + (ch) * 64;                                       \
    _Pragma("unroll")                                                           \
    for (int it = 0; it < 4; it++) {                                            \
        cp16(as_ + (st_row + it * 32) * 64 + st_sw, ap + (size_t)(it * 32) * K);\
        cp16(bs_ + (st_row + it * 32) * 64 + st_sw, bp + (size_t)(it * 32) * K);\
    }                                                                           \
} while (0)

    const int lsw = lane & 7;
    const int rA  = (lane & 7) + (lane & 8);
    const int rB  = (lane & 7) + ((lane & 16) >> 1);
    const int cA  = (lane >> 4) & 1;
    const int cB  = (lane >> 3) & 1;

    float cf[4][4][4];
    #pragma unroll
    for (int i = 0; i < 4; i++)
        #pragma unroll
        for (int j = 0; j < 4; j++)
            { cf[i][j][0] = 0.f; cf[i][j][1] = 0.f; cf[i][j][2] = 0.f; cf[i][j][3] = 0.f; }

    HSTAGE(0, 0);
    CP_COMMIT();

    for (int c = 0; c < nch; c++) {
        if (c + 1 < nch) { HSTAGE(c + 1, (c + 1) & 1); CP_COMMIT(); CP_WAIT1(); }
        else             { CP_WAIT0(); }
        __syncthreads();

        const uint32_t ab = smem_u32(As + (c & 1) * 8192);
        const uint32_t bb = smem_u32(Bs + (c & 1) * 8192);

        #pragma unroll
        for (int kk = 0; kk < 4; kk++) {
            const uint32_t sA = (uint32_t)(((kk * 2 + cA) ^ lsw) * 16);
            const uint32_t sB = (uint32_t)(((kk * 2 + cB) ^ lsw) * 16);
            uint32_t af[4][4], bf[2][4];
            #pragma unroll
            for (int mt = 0; mt < 4; mt++)
                LDSM4(af[mt][0], af[mt][1], af[mt][2], af[mt][3],
                      ab + (uint32_t)(wm + mt * 16 + rA) * 128u + sA);
            #pragma unroll
            for (int p = 0; p < 2; p++)
                LDSM4(bf[p][0], bf[p][1], bf[p][2], bf[p][3],
                      bb + (uint32_t)(wn + p * 16 + rB) * 128u + sB);
            #pragma unroll
            for (int mt = 0; mt < 4; mt++)
                #pragma unroll
                for (int nt = 0; nt < 4; nt++)
                    mma_h(cf[mt][nt], af[mt], &bf[nt >> 1][(nt & 1) * 2]);
        }
        __syncthreads();
    }
#undef HSTAGE

    #pragma unroll
    for (int mt = 0; mt < 4; mt++) {
        int row = m0 + wm + mt * 16 + (lane >> 2);
        #pragma unroll
        for (int nt = 0; nt < 4; nt++) {
            int col = n0 + wn + nt * 8 + (lane & 3) * 2;
            if (col < N) {
                #pragma unroll
                for (int hh = 0; hh < 2; hh++) {
                    int r = row + hh * 8;
                    float v0 = cf[mt][nt][hh * 2 + 0];
                    float v1 = cf[mt][nt][hh * 2 + 1];
                    if (bias) { v0 += bias[col]; v1 += bias[col + 1]; }
                    if (act == 1) {
                        v0 = 0.5f * v0 * (1.0f + erff(v0 * 0.70710678118654752f));
                        v1 = 0.5f * v1 * (1.0f + erff(v1 * 0.70710678118654752f));
                    } else if (act == 2) {
                        v0 = tanhf(v0); v1 = tanhf(v1);
                    }
                    if (resid) {
                        v0 += resid[(size_t)r * N + col];
                        v1 += resid[(size_t)r * N + col + 1];
                    }
                    if (C)  *(float2*)(C + (size_t)r * N + col) = make_float2(v0, v1);
                    if (C2) *(__half2*)(C2 + (size_t)r * N + col) = __floats2half2_rn(v0, v1);
                }
            }
        }
    }
}

/* ================= V transpose per head: g_vT[b,h][d][l] ================= */
__global__ void k_vT()
{
    __shared__ __half t[64][72];
    int b = blockIdx.z, h = blockIdx.y, l0 = blockIdx.x * 64;
    int tid = threadIdx.x;   /* 256 */
    #pragma unroll
    for (int it = 0; it < 8; it++) {
        int idx = tid + it * 256;
        int l = idx >> 5, c2 = idx & 31;
        const __half2* src = (const __half2*)(g_qkvH + (size_t)(b * LSEQ + l0 + l) * 3 * DMODEL
                                              + 2 * DMODEL + h * DHEAD);
        *(__half2*)&t[l][c2 * 2] = src[c2];
    }
    __syncthreads();
    #pragma unroll
    for (int it = 0; it < 8; it++) {
        int idx = tid + it * 256;
        int d = idx >> 5, lc = (idx & 31) * 2;
        __half2 v; v.x = t[lc][d]; v.y = t[lc + 1][d];
        *(__half2*)(g_vT + ((size_t)(b * NHEAD + h) * DHEAD + d) * LSEQ + l0 + lc) = v;
    }
}

/* ================= tensor-core fused attention (P via SMEM) ================= */
__global__ __launch_bounds__(128)
void k_attn(const float* __restrict__ res_scale, int layer)
{
    const int b = blockIdx.z, h = blockIdx.y, q0 = blockIdx.x * 64;
    const int tid = threadIdx.x, wid = tid >> 5, lane = tid & 31;
    const float rs = res_scale[layer];

    __shared__ __half Qs[64 * 64];          /* reused as P buffer after tile 0 */
    __shared__ __half Ks[2][64 * 64];
    __shared__ __half Vs[2][64 * 64];
    __shared__ float pvs[64];

    const int srow = tid >> 3;
    const int sc   = tid & 7;
    const uint32_t sdst = (uint32_t)((sc ^ (srow & 7)) * 8);

    /* stage Q (rows q0+) and KV tile 0 (rows 0+  -- NOT q0!) */
    {
        const __half* qg = g_qkvH + (size_t)(b * LSEQ + q0 + srow) * 3 * DMODEL + h * DHEAD + sc * 8;
        const __half* kg = g_qkvH + (size_t)(b * LSEQ + srow) * 3 * DMODEL + DMODEL + h * DHEAD + sc * 8;
        const __half* vg = g_vT + ((size_t)(b * NHEAD + h) * DHEAD + srow) * LSEQ + sc * 8;
        #pragma unroll
        for (int it = 0; it < 4; it++) {
            size_t off = (size_t)(it * 16) * 3 * DMODEL;
            cp16(Qs + (srow + it * 16) * 64 + sdst, qg + off);
            cp16(Ks[0] + (srow + it * 16) * 64 + sdst, kg + off);
            cp16(Vs[0] + (srow + it * 16) * 64 + sdst, vg + (size_t)(it * 16) * LSEQ);
        }
    }
    CP_COMMIT();

    const int lsw = lane & 7;
    const int rA  = (lane & 7) + (lane & 8);
    const int rB  = (lane & 7) + ((lane & 16) >> 1);
    const int cA  = (lane >> 4) & 1;
    const int cB  = (lane >> 3) & 1;
    const int wm  = wid * 16;
    const int g   = lane >> 2;
    const int tq  = lane & 3;

    const int gr1 = q0 + wm + g;
    const float pq1 = g_pv[(size_t)(b * LSEQ + gr1) * NHEAD + h];
    const float pq2 = g_pv[(size_t)(b * LSEQ + gr1 + 8) * NHEAD + h];

    float o[8][4];
    #pragma unroll
    for (int i = 0; i < 8; i++)
        { o[i][0] = 0.f; o[i][1] = 0.f; o[i][2] = 0.f; o[i][3] = 0.f; }
    float m1 = -1e30f, m2 = -1e30f, d1 = 0.f, d2 = 0.f;
    uint32_t qa[4][4];

    /* per-thread P store pointers (swizzled row-major, warp-local rows) */
    __half* P1 = Qs + (wm + g) * 64 + tq * 2;
    __half* P2 = P1 + 8 * 64;
    const int psw = (g & 7) * 8;   /* chunk swizzle, same for rows g and g+8 */

    for (int j = 0; j < LSEQ / 64; j++) {
        const int buf = j & 1;
        if (j + 1 < LSEQ / 64) {
            const int nbuf = buf ^ 1;
            const int kv1 = (j + 1) * 64;
            const __half* kg = g_qkvH + (size_t)(b * LSEQ + kv1 + srow) * 3 * DMODEL
                               + DMODEL + h * DHEAD + sc * 8;
            const __half* vg = g_vT + ((size_t)(b * NHEAD + h) * DHEAD + srow) * LSEQ + kv1 + sc * 8;
            #pragma unroll
            for (int it = 0; it < 4; it++) {
                cp16(Ks[nbuf] + (srow + it * 16) * 64 + sdst, kg + (size_t)(it * 16) * 3 * DMODEL);
                cp16(Vs[nbuf] + (srow + it * 16) * 64 + sdst, vg + (size_t)(it * 16) * LSEQ);
            }
            CP_COMMIT();
            CP_WAIT1();
        } else {
            CP_WAIT0();
        }
        if (tid < 64)
            pvs[tid] = g_pv[(size_t)(b * LSEQ + j * 64 + tid) * NHEAD + h];
        __syncthreads();

        if (j == 0) {   /* Q fragments once; Qs becomes the P buffer after this */
            const uint32_t qb = smem_u32(Qs);
            #pragma unroll
            for (int ks = 0; ks < 4; ks++)
                LDSM4(qa[ks][0], qa[ks][1], qa[ks][2], qa[ks][3],
                      qb + (uint32_t)(wm + rA) * 128u + (uint32_t)(((ks * 2 + cA) ^ lsw) * 16));
        }

        /* S = Q K^T */
        float s[8][4];
        #pragma unroll
        for (int i = 0; i < 8; i++)
            { s[i][0] = 0.f; s[i][1] = 0.f; s[i][2] = 0.f; s[i][3] = 0.f; }
        {
            const uint32_t kb = smem_u32(Ks[buf]);
            #pragma unroll
            for (int ks = 0; ks < 4; ks++) {
                const uint32_t sB = (uint32_t)(((ks * 2 + cB) ^ lsw) * 16);
                uint32_t bf[4][4];
                #pragma unroll
                for (int nb2 = 0; nb2 < 4; nb2++)
                    LDSM4(bf[nb2][0], bf[nb2][1], bf[nb2][2], bf[nb2][3],
                          kb + (uint32_t)(nb2 * 16 + rB) * 128u + sB);
                #pragma unroll
                for (int nt = 0; nt < 8; nt++)
                    mma_h(s[nt], qa[ks], &bf[nt >> 1][(nt & 1) * 2]);
            }
        }

        /* exact phase penalty + online softmax */
        float tmax1 = -1e30f, tmax2 = -1e30f;
        #pragma unroll
        for (int nt = 0; nt < 8; nt++) {
            float k0 = pvs[nt * 8 + tq * 2];
            float k1 = pvs[nt * 8 + tq * 2 + 1];
            float u;
            u = pq1 - k0; s[nt][0] = s[nt][0] * 0.125f - rs * u * u;
            u = pq1 - k1; s[nt][1] = s[nt][1] * 0.125f - rs * u * u;
            u = pq2 - k0; s[nt][2] = s[nt][2] * 0.125f - rs * u * u;
            u = pq2 - k1; s[nt][3] = s[nt][3] * 0.125f - rs * u * u;
            tmax1 = fmaxf(tmax1, fmaxf(s[nt][0], s[nt][1]));
            tmax2 = fmaxf(tmax2, fmaxf(s[nt][2], s[nt][3]));
        }
        tmax1 = fmaxf(tmax1, __shfl_xor_sync(0xffffffffu, tmax1, 1));
        tmax1 = fmaxf(tmax1, __shfl_xor_sync(0xffffffffu, tmax1, 2));
        tmax2 = fmaxf(tmax2, __shfl_xor_sync(0xffffffffu, tmax2, 1));
        tmax2 = fmaxf(tmax2, __shfl_xor_sync(0xffffffffu, tmax2, 2));
        float mn1 = fmaxf(m1, tmax1), mn2 = fmaxf(m2, tmax2);
        float c1 = __expf(m1 - mn1), c2 = __expf(m2 - mn2);
        m1 = mn1; m2 = mn2;
        d1 *= c1; d2 *= c2;
        #pragma unroll
        for (int nt = 0; nt < 8; nt++) {
            o[nt][0] *= c1; o[nt][1] *= c1;
            o[nt][2] *= c2; o[nt][3] *= c2;
        }
        /* p -> fp16 via SMEM (same swizzled layout as GEMM A tiles) */
        #pragma unroll
        for (int nt = 0; nt < 8; nt++) {
            float p0 = __expf(s[nt][0] - m1), p1 = __expf(s[nt][1] - m1);
            float p2 = __expf(s[nt][2] - m2), p3 = __expf(s[nt][3] - m2);
            d1 += p0 + p1; d2 += p2 + p3;
            int chunk = (nt ^ psw / 8) * 8;   /* nt ^ (g&7), in halves */
            *(__half2*)(P1 + chunk) = __floats2half2_rn(p0, p1);
            *(__half2*)(P2 + chunk) = __floats2half2_rn(p2, p3);
        }
        __syncwarp();

        /* O += P @ Vt : A fragments of P via standard ldmatrix path */
        {
            const uint32_t pb = smem_u32(Qs);
            const uint32_t vb = smem_u32(Vs[buf]);
            #pragma unroll
            for (int ks = 0; ks < 4; ks++) {
                uint32_t pa[4];
                LDSM4(pa[0], pa[1], pa[2], pa[3],
                      pb + (uint32_t)(wm + rA) * 128u + (uint32_t)(((ks * 2 + cA) ^ lsw) * 16));
                const uint32_t sB = (uint32_t)(((ks * 2 + cB) ^ lsw) * 16);
                uint32_t vf[4][4];
                #pragma unroll
                for (int nb2 = 0; nb2 < 4; nb2++)
                    LDSM4(vf[nb2][0], vf[nb2][1], vf[nb2][2], vf[nb2][3],
                          vb + (uint32_t)(nb2 * 16 + rB) * 128u + sB);
                #pragma unroll
                for (int nt = 0; nt < 8; nt++)
                    mma_h(o[nt], pa, &vf[nt >> 1][(nt & 1) * 2]);
            }
        }
        __syncthreads();
    }

    d1 += __shfl_xor_sync(0xffffffffu, d1, 1);
    d1 += __shfl_xor_sync(0xffffffffu, d1, 2);
    d2 += __shfl_xor_sync(0xffffffffu, d2, 1);
    d2 += __shfl_xor_sync(0xffffffffu, d2, 2);
    float i1 = 1.0f / d1, i2 = 1.0f / d2;
    __half* o1 = g_aoH + (size_t)(b * LSEQ + gr1) * DMODEL + h * DHEAD + tq * 2;
    __half* o2 = o1 + (size_t)8 * DMODEL;
    #pragma unroll
    for (int nt = 0; nt < 8; nt++) {
        *(__half2*)(o1 + nt * 8) = __floats2half2_rn(o[nt][0] * i1, o[nt][1] * i1);
        *(__half2*)(o2 + nt * 8) = __floats2half2_rn(o[nt][2] * i2, o[nt][3] * i2);
    }
}

/* ================= weight transpose + fp16 convert ================= */
__global__ void k_cvtT(const float* __restrict__ src, __half* __restrict__ dst,
                       int K, int N)
{
    __shared__ float t[32][33];
    int n0 = blockIdx.x * 32, k0 = blockIdx.y * 32;
    int tx = threadIdx.x, ty = threadIdx.y;
    #pragma unroll
    for (int i = 0; i < 4; i++)
        t[ty + i * 8][tx] = src[(size_t)(k0 + ty + i * 8) * N + n0 + tx];
    __syncthreads();
    #pragma unroll
    for (int i = 0; i < 4; i++)
        dst[(size_t)(n0 + ty + i * 8) * K + k0 + tx] = __float2half_rn(t[tx][ty + i * 8]);
}

/* ================= embed -> fp16 [VPAD][D] with zero pad ================= */
__global__ void k_cvtE(const float* __restrict__ src)
{
    size_t stride = (size_t)gridDim.x * blockDim.x;
    size_t tot8 = (size_t)VPAD * DMODEL / 8;
    for (size_t i = (size_t)blockIdx.x * blockDim.x + threadIdx.x; i < tot8; i += stride) {
        size_t e = i * 8;
        size_t row = e / DMODEL;
        __half2 h[4];
        if (row < VOCAB) {
            float4 v0 = *(const float4*)(src + e);
            float4 v1 = *(const float4*)(src + e + 4);
            h[0] = __floats2half2_rn(v0.x, v0.y);
            h[1] = __floats2half2_rn(v0.z, v0.w);
            h[2] = __floats2half2_rn(v1.x, v1.y);
            h[3] = __floats2half2_rn(v1.z, v1.w);
        } else {
            h[0] = h[1] = h[2] = h[3] = __float2half2_rn(0.f);
        }
        *(uint4*)(g_embH + e) = *(uint4*)h;
    }
}

/* ================= embedding + positional ================= */
__global__ void k_embed(const int* __restrict__ ids,
                        const float* __restrict__ emb,
                        const float* __restrict__ pos)
{
    int r = blockIdx.x;
    int l = r % LSEQ;
    int id = ids[r];
    const float4* e4 = (const float4*)(emb + (size_t)id * DMODEL);
    const float4* p4 = (const float4*)(pos + (size_t)l * DMODEL);
    float4* x4 = (float4*)(g_x + (size_t)r * DMODEL);
    for (int k = threadIdx.x; k < DMODEL / 4; k += blockDim.x) {
        float4 e = e4[k], p = p4[k];
        float4 o;
        o.x = e.x * 32.0f + p.x;
        o.y = e.y * 32.0f + p.y;
        o.z = e.z * 32.0f + p.z;
        o.w = e.w * 32.0f + p.w;
        x4[k] = o;
    }
}

/* ================= R-grammar gate + xm modulation ================= */
__global__ void k_rg_xm(const float* __restrict__ rg_w,
                        const float* __restrict__ rg_b,
                        int layer, float* __restrict__ gs_out)
{
    int r = blockIdx.x;
    int t = threadIdx.x;
    const float* xr = g_x + (size_t)r * DMODEL;
    const float4* w4 = (const float4*)(rg_w + (size_t)layer * DMODEL * 4);
    float s0 = 0.f, s1 = 0.f, s2 = 0.f, s3 = 0.f;
    for (int k = t; k < DMODEL; k += 128) {
        float xv = xr[k];
        float4 w = w4[k];
        s0 += xv * w.x; s1 += xv * w.y; s2 += xv * w.z; s3 += xv * w.w;
    }
    for (int o = 16; o > 0; o >>= 1) {
        s0 += __shfl_down_sync(0xffffffffu, s0, o);
        s1 += __shfl_down_sync(0xffffffffu, s1, o);
        s2 += __shfl_down_sync(0xffffffffu, s2, o);
        s3 += __shfl_down_sync(0xffffffffu, s3, o);
    }
    __shared__ float red[4][4];
    __shared__ float mscale;
    int w = t >> 5, lane = t & 31;
    if (lane == 0) { red[w][0] = s0; red[w][1] = s1; red[w][2] = s2; red[w][3] = s3; }
    __syncthreads();
    if (t == 0) {
        float sum4 = 0.f;
        float* gsp = gs_out + ((size_t)layer * NROWS + r) * 4;
        #pragma unroll
        for (int n = 0; n < 4; n++) {
            float a = red[0][n] + red[1][n] + red[2][n] + red[3][n] + rg_b[layer * 4 + n];
            float sg = 1.0f / (1.0f + expf(-a));
            gsp[n] = sg;
            sum4 += sg;
        }
        mscale = 1.0f + 0.1f * (sum4 * 0.25f);
    }
    __syncthreads();
    float ms = mscale;
    const float4* x4 = (const float4*)xr;
    float4* xm4 = (float4*)(g_xm + (size_t)r * DMODEL);
    for (int k = t; k < DMODEL / 4; k += 128) {
        float4 v = x4[k];
        v.x *= ms; v.y *= ms; v.z *= ms; v.w *= ms;
        xm4[k] = v;
    }
}

/* ================= LayerNorm: fp16 main output + optional fp32 copy ======= */
__global__ void k_ln(const float* __restrict__ in,
                     const float* __restrict__ g,
                     const float* __restrict__ b,
                     __half* __restrict__ outh,
                     float* __restrict__ outf)
{
    int r = blockIdx.x, t = threadIdx.x;
    const float4* i4 = (const float4*)(in + (size_t)r * DMODEL);
    float4 v = i4[t];
    float s = v.x + v.y + v.z + v.w;
    float q = v.x * v.x + v.y * v.y + v.z * v.z + v.w * v.w;
    for (int o = 16; o > 0; o >>= 1) {
        s += __shfl_down_sync(0xffffffffu, s, o);
        q += __shfl_down_sync(0xffffffffu, q, o);
    }
    __shared__ float sr[8], qr[8];
    __shared__ float smean, sinv;
    if ((t & 31) == 0) { sr[t >> 5] = s; qr[t >> 5] = q; }
    __syncthreads();
    if (t == 0) {
        float S = 0.f, Q = 0.f;
        #pragma unroll
        for (int i = 0; i < 8; i++) { S += sr[i]; Q += qr[i]; }
        float mean = S * (1.0f / DMODEL);
        float var = Q * (1.0f / DMODEL) - mean * mean;
        smean = mean;
        sinv = rsqrtf(var + 1e-5f);
    }
    __syncthreads();
    float mean = smean, inv = sinv;
    float4 gg = ((const float4*)g)[t];
    float4 bb = ((const float4*)b)[t];
    float4 o;
    o.x = (v.x - mean) * inv * gg.x + bb.x;
    o.y = (v.y - mean) * inv * gg.y + bb.y;
    o.z = (v.z - mean) * inv * gg.z + bb.z;
    o.w = (v.w - mean) * inv * gg.w + bb.w;
    __half2* hp = (__half2*)(outh + (size_t)r * DMODEL + t * 4);
    hp[0] = __floats2half2_rn(o.x, o.y);
    hp[1] = __floats2half2_rn(o.z, o.w);
    if (outf)
        ((float4*)(outf + (size_t)r * DMODEL))[t] = o;
}

/* ================= phase vector (fp16 a_in) ================= */
__global__ void k_ph(const float* __restrict__ ph_w,
                     const float* __restrict__ ph_b,
                     const float* __restrict__ ph_scale, int layer)
{
    int r = blockIdx.x, t = threadIdx.x;
    const __half* ar = g_ainH + (size_t)r * DMODEL;
    const float4* w4 = (const float4*)(ph_w + (size_t)layer * DMODEL * NHEAD);
    float acc[16];
    #pragma unroll
    for (int n = 0; n < 16; n++) acc[n] = 0.f;
    for (int k = t; k < DMODEL; k += 128) {
        float a = __half2float(ar[k]);
        #pragma unroll
        for (int q = 0; q < 4; q++) {
            float4 w = w4[k * 4 + q];
            acc[q * 4 + 0] += a * w.x;
            acc[q * 4 + 1] += a * w.y;
            acc[q * 4 + 2] += a * w.z;
            acc[q * 4 + 3] += a * w.w;
        }
    }
    __shared__ float red[128][16];
    #pragma unroll
    for (int n = 0; n < 16; n++) red[t][n] = acc[n];
    __syncthreads();
    for (int s = 64; s >= 1; s >>= 1) {
        if (t < s) {
            #pragma unroll
            for (int n = 0; n < 16; n++) red[t][n] += red[t + s][n];
        }
        __syncthreads();
    }
    if (t < 16) {
        float v = red[0][t] + ph_b[layer * NHEAD + t];
        g_pv[(size_t)r * NHEAD + t] = tanhf(ph_scale[layer] * v);
    }
}

/* ================= boundary scalar ================= */
__global__ void k_bnd2(const float* __restrict__ w2,
                       const float* __restrict__ b2,
                       float* __restrict__ ss_out, int layer)
{
    int r = blockIdx.x, t = threadIdx.x;
    const float* hr = g_bndh + (size_t)r * HIDB;
    float s = 0.f;
    for (int k = t; k < HIDB; k += 128) s += hr[k] * w2[k];
    for (int o = 16; o > 0; o >>= 1) s += __shfl_down_sync(0xffffffffu, s, o);
    __shared__ float red[4];
    if ((t & 31) == 0) red[t >> 5] = s;
    __syncthreads();
    if (t == 0) {
        float v = red[0] + red[1] + red[2] + red[3] + b2[0];
        ss_out[(size_t)layer * NROWS + r] = 1.0f / (1.0f + expf(-v));
    }
}

/* ================= means over layers ================= */
__global__ void k_means(float* out)
{
    int idx = blockIdx.x * 256 + threadIdx.x;
    if (idx < NROWS * 4) {
        float s = 0.f;
        #pragma unroll
        for (int l = 0; l < NLAY; l++) s += out[OUT_GS + (size_t)l * NROWS * 4 + idx];
        out[OUT_GSM + idx] = s * (1.0f / NLAY);
    }
    int idx2 = idx - NROWS * 4;
    if (idx2 >= 0 && idx2 < NROWS) {
        float s = 0.f;
        #pragma unroll
        for (int l = 0; l < NLAY; l++) s += out[OUT_SS + (size_t)l * NROWS + idx2];
        out[OUT_SSM + idx2] = s * (1.0f / NLAY);
    }
}

/* ================= host ================= */
#define GEMM_SMEM 65536

extern "C" void kernel_launch(void* const* d_in, const int* in_sizes, int n_in,
                              void* d_out, int out_size)
{
    const int*   ids      = (const int*)  d_in[0];
    const float* embed    = (const float*)d_in[1];
    const float* pos_enc  = (const float*)d_in[2];
    const float* rg_w     = (const float*)d_in[3];
    const float* rg_b     = (const float*)d_in[4];
    const float* qkv_w    = (const float*)d_in[5];
    const float* qkv_b    = (const float*)d_in[6];
    const float* out_w    = (const float*)d_in[7];
    const float* out_b    = (const float*)d_in[8];
    const float* ph_w     = (const float*)d_in[9];
    const float* ph_b     = (const float*)d_in[10];
    const float* resscale = (const float*)d_in[11];
    const float* ph_scale = (const float*)d_in[12];
    const float* ff1_w    = (const float*)d_in[13];
    const float* ff1_b    = (const float*)d_in[14];
    const float* ff2_w    = (const float*)d_in[15];
    const float* ff2_b    = (const float*)d_in[16];
    const float* n1_g     = (const float*)d_in[17];
    const float* n1_b     = (const float*)d_in[18];
    const float* n2_g     = (const float*)d_in[19];
    const float* n2_b     = (const float*)d_in[20];
    const float* bnd_w1   = (const float*)d_in[21];
    const float* bnd_b1   = (const float*)d_in[22];
    const float* bnd_w2   = (const float*)d_in[23];
    const float* bnd_b2   = (const float*)d_in[24];
    const float* fn_g     = (const float*)d_in[25];
    const float* fn_b     = (const float*)d_in[26];
    float* out = (float*)d_out;

    float *px, *pxm, *pbndh;
    __half *painH, *paoH, *pffhH, *pqkvH, *pwh, *pembH;
    cudaGetSymbolAddress((void**)&px,    g_x);
    cudaGetSymbolAddress((void**)&pxm,   g_xm);
    cudaGetSymbolAddress((void**)&pbndh, g_bndh);
    cudaGetSymbolAddress((void**)&painH, g_ainH);
    cudaGetSymbolAddress((void**)&paoH,  g_aoH);
    cudaGetSymbolAddress((void**)&pffhH, g_ffhH);
    cudaGetSymbolAddress((void**)&pqkvH, g_qkvH);
    cudaGetSymbolAddress((void**)&pwh,   g_wh);
    cudaGetSymbolAddress((void**)&pembH, g_embH);

    cudaFuncSetAttribute(k_hgemm, cudaFuncAttributeMaxDynamicSharedMemorySize, GEMM_SMEM);

    dim3 tb(32, 8);
    for (int i = 0; i < NLAY; i++) {
        k_cvtT<<<dim3(3 * DMODEL / 32, DMODEL / 32), tb>>>(
            qkv_w + (size_t)i * DMODEL * 3 * DMODEL,
            pwh + W_QKV + (size_t)i * 3 * DMODEL * DMODEL, DMODEL, 3 * DMODEL);
        k_cvtT<<<dim3(DMODEL / 32, DMODEL / 32), tb>>>(
            out_w + (size_t)i * DMODEL * DMODEL,
            pwh + W_OUT + (size_t)i * DMODEL * DMODEL, DMODEL, DMODEL);
        k_cvtT<<<dim3(FFDIM / 32, DMODEL / 32), tb>>>(
            ff1_w + (size_t)i * DMODEL * FFDIM,
            pwh + W_FF1 + (size_t)i * DMODEL * FFDIM, DMODEL, FFDIM);
        k_cvtT<<<dim3(DMODEL / 32, FFDIM / 32), tb>>>(
            ff2_w + (size_t)i * FFDIM * DMODEL,
            pwh + W_FF2 + (size_t)i * FFDIM * DMODEL, FFDIM, DMODEL);
    }
    k_cvtT<<<dim3(HIDB / 32, DMODEL / 32), tb>>>(bnd_w1, pwh + W_BND, DMODEL, HIDB);
    k_cvtE<<<2048, 256>>>(embed);
    k_embed<<<NROWS, 256>>>(ids, embed, pos_enc);

    for (int i = 0; i < NLAY; i++) {
        k_rg_xm<<<NROWS, 128>>>(rg_w, rg_b, i, out + OUT_GS);
        k_ln<<<NROWS, 256>>>(pxm, n1_g + (size_t)i * DMODEL, n1_b + (size_t)i * DMODEL,
                             painH, (float*)0);
        /* QKV projection -> fp16 qkv */
        {
            dim3 grid((3 * DMODEL) / 128, NROWS / 128);
            k_hgemm<<<grid, 256, GEMM_SMEM>>>(painH, pwh + W_QKV + (size_t)i * 3 * DMODEL * DMODEL,
                                              qkv_b + (size_t)i * 3 * DMODEL, (const float*)0,
                                              (float*)0, pqkvH, NROWS, 3 * DMODEL, DMODEL, 0);
        }
        k_ph<<<NROWS, 128>>>(ph_w, ph_b, ph_scale, i);
        k_vT<<<dim3(LSEQ / 64, NHEAD, NB), 256>>>();
        {
            dim3 grid(LSEQ / 64, NHEAD, NB);
            k_attn<<<grid, 128>>>(resscale, i);
        }
        /* out projection + residual (xm) -> px fp32 */
        {
            dim3 grid(DMODEL / 128, NROWS / 128);
            k_hgemm<<<grid, 256, GEMM_SMEM>>>(paoH, pwh + W_OUT + (size_t)i * DMODEL * DMODEL,
                                              out_b + (size_t)i * DMODEL, pxm,
                                              px, (__half*)0, NROWS, DMODEL, DMODEL, 0);
        }
        k_ln<<<NROWS, 256>>>(px, n2_g + (size_t)i * DMODEL, n2_b + (size_t)i * DMODEL,
                             painH, (float*)0);
        /* FF1 + GELU -> fp16 hidden */
        {
            dim3 grid(FFDIM / 128, NROWS / 128);
            k_hgemm<<<grid, 256, GEMM_SMEM>>>(painH, pwh + W_FF1 + (size_t)i * DMODEL * FFDIM,
                                              ff1_b + (size_t)i * FFDIM, (const float*)0,
                                              (float*)0, pffhH, NROWS, FFDIM, DMODEL, 1);
        }
        /* FF2 + residual -> px fp32 AND fp16 copy for boundary */
        {
            dim3 grid(DMODEL / 128, NROWS / 128);
            k_hgemm<<<grid, 256, GEMM_SMEM>>>(pffhH, pwh + W_FF2 + (size_t)i * FFDIM * DMODEL,
                                              ff2_b + (size_t)i * DMODEL, px,
                                              px, painH, NROWS, DMODEL, FFDIM, 0);
        }
        /* boundary MLP layer 1 (tanh) -> fp32 hidden */
        {
            dim3 grid(HIDB / 128, NROWS / 128);
            k_hgemm<<<grid, 256, GEMM_SMEM>>>(painH, pwh + W_BND, bnd_b1, (const float*)0,
                                              pbndh, (__half*)0, NROWS, HIDB, DMODEL, 2);
        }
        k_bnd2<<<NROWS, 128>>>(bnd_w2, bnd_b2, out + OUT_SS, i);
    }

    /* final LN -> fp32 x output + fp16 copy for logits A */
    k_ln<<<NROWS, 256>>>(px, fn_g, fn_b, painH, out + OUT_X);

    {
        dim3 grid(VPAD / 128, NROWS / 128);
        k_hgemm<<<grid, 256, GEMM_SMEM>>>(painH, pembH, (const float*)0, (const float*)0,
                                          out + OUT_LOGITS, (__half*)0, NROWS, VOCAB, DMODEL, 0);
    }

    k_means<<<(NROWS * 4 + NROWS + 255) / 256, 256>>>(out);
}